// round 10
// baseline (speedup 1.0000x reference)
#include <cuda_runtime.h>
#include <cuda_fp16.h>
#include <mma.h>
#include <math.h>
#include <stdint.h>

using namespace nvcuda;

#define D 128
#define MAXN 50432
#define MAXE 1700000
#define LO_SCALE 1024.0f
#define INV_LO (1.0f / 1024.0f)

// ---------------- scratch (device globals: allocation-free) ----------------
__device__ float g_dinv[MAXN];                 // deg -> rsqrt(deg)
__device__ int   g_cnt[MAXN];                  // in-degree histogram
__device__ int   g_off[MAXN + 1];              // CSR offsets
__device__ int   g_cur[MAXN];                  // placement cursors
__device__ int   g_tmp[MAXN];                  // scan scratch
__device__ int   g_part[64];                   // scan block partials
__device__ int2  g_srt[MAXE];                  // packed (row, norm) per edge, grouped by col
__device__ __half g_xhh[(size_t)MAXN * 256];   // [x|h] fp16 gather source
__device__ __half g_rhh[(size_t)MAXN * D];     // r*h fp16 gather source
__device__ __half g_axh[(size_t)MAXN * 256];   // [S@x | S@h]  (GEMM1 A, fp16)
__device__ __half g_aSr[(size_t)MAXN * D];     // S@(r*h)      (GEMM2 A, fp16)
__device__ float g_P[(size_t)MAXN * 384];      // GEMM1 out: [z_pre | r_pre | xh_part]
__device__ float g_Q[(size_t)MAXN * D];        // GEMM2 out
__device__ float g_z[(size_t)MAXN * D];        // z gate
__device__ __half g_W1h[2 * 384 * 256];        // GEMM1 B hi (n-major, per layer)
__device__ __half g_W1l[2 * 384 * 256];        // GEMM1 B lo*1024
__device__ __half g_W2h[2 * 128 * 128];        // GEMM2 B hi
__device__ __half g_W2l[2 * 128 * 128];        // GEMM2 B lo*1024

__device__ __forceinline__ float sigmoidf(float x) { return 1.0f / (1.0f + expf(-x)); }

// ---------------- degree / histogram ----------------
__global__ void k_deg_init(int n) {
    int i = blockIdx.x * blockDim.x + threadIdx.x;
    if (i < n) { g_dinv[i] = 1.0f; g_cnt[i] = 0; }
}
__global__ void k_deg_edges(const int* __restrict__ coli, const float* __restrict__ w, int E) {
    int e = blockIdx.x * blockDim.x + threadIdx.x;
    if (e < E) {
        int c = coli[e];
        atomicAdd(&g_dinv[c], w[e]);
        atomicAdd(&g_cnt[c], 1);
    }
}

// ---------------- multi-block scan (phase 1 also finalizes dinv) ----------------
__global__ void __launch_bounds__(1024)
k_scan1(int n) {
    __shared__ int warpsum[32];
    int i = blockIdx.x * 1024 + threadIdx.x;
    int lane = threadIdx.x & 31, wid = threadIdx.x >> 5;
    if (i < n) {                      // fold old k_dinv in
        float d = g_dinv[i];
        g_dinv[i] = (d > 0.0f) ? rsqrtf(d) : 0.0f;
    }
    int v = (i < n) ? g_cnt[i] : 0;
    int x = v;
#pragma unroll
    for (int o = 1; o < 32; o <<= 1) {
        int t = __shfl_up_sync(~0u, x, o);
        if (lane >= o) x += t;
    }
    if (lane == 31) warpsum[wid] = x;
    __syncthreads();
    if (wid == 0) {
        int s = warpsum[lane];
#pragma unroll
        for (int o = 1; o < 32; o <<= 1) {
            int t = __shfl_up_sync(~0u, s, o);
            if (lane >= o) s += t;
        }
        warpsum[lane] = s;
    }
    __syncthreads();
    int incl = x + ((wid > 0) ? warpsum[wid - 1] : 0);
    if (i < n) g_tmp[i] = incl;
    if (threadIdx.x == 1023) g_part[blockIdx.x] = incl;
}
__global__ void k_scan2(int nb) {
    __shared__ int sm[64];
    int t = threadIdx.x;
    sm[t] = (t < nb) ? g_part[t] : 0;
    __syncthreads();
    for (int o = 1; o < 64; o <<= 1) {
        int v = (t >= o) ? sm[t - o] : 0;
        __syncthreads();
        sm[t] += v;
        __syncthreads();
    }
    g_part[t] = (t > 0) ? sm[t - 1] : 0;
}
__global__ void k_scan3(int n) {
    int i = blockIdx.x * blockDim.x + threadIdx.x;
    if (i >= n) return;
    int off = g_tmp[i] + g_part[i >> 10];
    g_off[i + 1] = off;
    g_cur[i] = off - g_cnt[i];
    if (i == 0) g_off[0] = 0;
}

// ---------------- placement scatter ----------------
__global__ void k_place(const int* __restrict__ rowi, const int* __restrict__ coli,
                        const float* __restrict__ w, int E) {
    int e = blockIdx.x * blockDim.x + threadIdx.x;
    if (e >= E) return;
    int r = rowi[e], c = coli[e];
    float nrm = w[e] * __ldg(g_dinv + r) * __ldg(g_dinv + c);
    int pos = atomicAdd(&g_cur[c], 1);
    g_srt[pos] = make_int2(r, __float_as_int(nrm));
}

// ---------------- weight build: all layers, fp16 hi + scaled lo, n-major ----------------
__global__ void k_build_wt1(const float* __restrict__ Wxz, const float* __restrict__ Whz,
                            const float* __restrict__ Wxr, const float* __restrict__ Whr,
                            const float* __restrict__ Wxh, int L) {
    int idx = blockIdx.x * blockDim.x + threadIdx.x;
    if (idx >= L * 384 * 256) return;
    int layer = idx / (384 * 256);
    int rem = idx % (384 * 256);
    int n = rem / 256, k = rem % 256;
    int blk = n >> 7, nn = n & 127;
    size_t wo = (size_t)layer * D * D;
    float v;
    if (blk == 0)      v = (k < 128) ? Wxz[wo + k * 128 + nn] : Whz[wo + (k - 128) * 128 + nn];
    else if (blk == 1) v = (k < 128) ? Wxr[wo + k * 128 + nn] : Whr[wo + (k - 128) * 128 + nn];
    else               v = (k < 128) ? Wxh[wo + k * 128 + nn] : 0.0f;
    __half hi = __float2half_rn(v);
    g_W1h[idx] = hi;
    g_W1l[idx] = __float2half_rn((v - __half2float(hi)) * LO_SCALE);
}
__global__ void k_build_wt2(const float* __restrict__ Whh, int L) {
    int idx = blockIdx.x * blockDim.x + threadIdx.x;
    if (idx >= L * 128 * 128) return;
    int layer = idx / (128 * 128);
    int rem = idx % (128 * 128);
    int n = rem / 128, k = rem % 128;
    float v = Whh[(size_t)layer * D * D + k * 128 + n];
    __half hi = __float2half_rn(v);
    g_W2h[idx] = hi;
    g_W2l[idx] = __float2half_rn((v - __half2float(hi)) * LO_SCALE);
}

// ---------------- prep: pack [x|h] fp32 -> fp16 gather rows (layer 0 only) ----------------
__global__ void k_prep(const float* __restrict__ x, const float* __restrict__ h, int n) {
    int idx = blockIdx.x * blockDim.x + threadIdx.x;
    if (idx >= n * 32) return;
    int m = idx >> 5, j = idx & 31;
    const float4* src = (j < 16) ? (const float4*)x + (size_t)m * 32 + 2 * j
                                 : (const float4*)h + (size_t)m * 32 + 2 * (j - 16);
    float4 a = __ldg(src), b = __ldg(src + 1);
    __half2 h0 = __floats2half2_rn(a.x, a.y), h1 = __floats2half2_rn(a.z, a.w);
    __half2 h2 = __floats2half2_rn(b.x, b.y), h3 = __floats2half2_rn(b.z, b.w);
    uint4 o;
    o.x = *(uint32_t*)&h0; o.y = *(uint32_t*)&h1; o.z = *(uint32_t*)&h2; o.w = *(uint32_t*)&h3;
    ((uint4*)g_xhh)[(size_t)m * 32 + j] = o;
}

// ---------------- CSR gather: 256-wide fp16 -> g_axh fp16, warp per node ----------------
__global__ void __launch_bounds__(256)
k_csr256(int n) {
    int node = (blockIdx.x * blockDim.x + threadIdx.x) >> 5;
    if (node >= n) return;
    int lane = threadIdx.x & 31;
    const uint4* src = (const uint4*)g_xhh;
    float di = __ldg(g_dinv + node);
    float s = di * di;
    float acc[8];
    {
        uint4 v = __ldg(src + (size_t)node * 32 + lane);
        float2 f0 = __half22float2(*(__half2*)&v.x), f1 = __half22float2(*(__half2*)&v.y);
        float2 f2 = __half22float2(*(__half2*)&v.z), f3 = __half22float2(*(__half2*)&v.w);
        acc[0] = s * f0.x; acc[1] = s * f0.y; acc[2] = s * f1.x; acc[3] = s * f1.y;
        acc[4] = s * f2.x; acc[5] = s * f2.y; acc[6] = s * f3.x; acc[7] = s * f3.y;
    }
    int e0 = __ldg(g_off + node), e1 = __ldg(g_off + node + 1);
#pragma unroll 4
    for (int e = e0; e < e1; e++) {
        int2 p = __ldg(g_srt + e);
        float nrm = __int_as_float(p.y);
        uint4 v = __ldg(src + (size_t)p.x * 32 + lane);
        float2 f0 = __half22float2(*(__half2*)&v.x), f1 = __half22float2(*(__half2*)&v.y);
        float2 f2 = __half22float2(*(__half2*)&v.z), f3 = __half22float2(*(__half2*)&v.w);
        acc[0] += nrm * f0.x; acc[1] += nrm * f0.y; acc[2] += nrm * f1.x; acc[3] += nrm * f1.y;
        acc[4] += nrm * f2.x; acc[5] += nrm * f2.y; acc[6] += nrm * f3.x; acc[7] += nrm * f3.y;
    }
    __half2 o0 = __floats2half2_rn(acc[0], acc[1]), o1 = __floats2half2_rn(acc[2], acc[3]);
    __half2 o2 = __floats2half2_rn(acc[4], acc[5]), o3 = __floats2half2_rn(acc[6], acc[7]);
    uint4 o;
    o.x = *(uint32_t*)&o0; o.y = *(uint32_t*)&o1; o.z = *(uint32_t*)&o2; o.w = *(uint32_t*)&o3;
    ((uint4*)g_axh)[(size_t)node * 32 + lane] = o;
}

// ---------------- CSR gather: 128-wide fp16 (g_rhh -> g_aSr fp16), warp per node -------
__global__ void __launch_bounds__(256)
k_csr128(int n) {
    int node = (blockIdx.x * blockDim.x + threadIdx.x) >> 5;
    if (node >= n) return;
    int lane = threadIdx.x & 31;
    const uint2* src = (const uint2*)g_rhh;
    float di = __ldg(g_dinv + node);
    float s = di * di;
    float acc[4];
    {
        uint2 v = __ldg(src + (size_t)node * 32 + lane);
        float2 f0 = __half22float2(*(__half2*)&v.x), f1 = __half22float2(*(__half2*)&v.y);
        acc[0] = s * f0.x; acc[1] = s * f0.y; acc[2] = s * f1.x; acc[3] = s * f1.y;
    }
    int e0 = __ldg(g_off + node), e1 = __ldg(g_off + node + 1);
#pragma unroll 4
    for (int e = e0; e < e1; e++) {
        int2 p = __ldg(g_srt + e);
        float nrm = __int_as_float(p.y);
        uint2 v = __ldg(src + (size_t)p.x * 32 + lane);
        float2 f0 = __half22float2(*(__half2*)&v.x), f1 = __half22float2(*(__half2*)&v.y);
        acc[0] += nrm * f0.x; acc[1] += nrm * f0.y; acc[2] += nrm * f1.x; acc[3] += nrm * f1.y;
    }
    __half2 o0 = __floats2half2_rn(acc[0], acc[1]), o1 = __floats2half2_rn(acc[2], acc[3]);
    uint2 o;
    o.x = *(uint32_t*)&o0; o.y = *(uint32_t*)&o1;
    ((uint2*)g_aSr)[(size_t)node * 32 + lane] = o;
}

// ---------------- WMMA fp16 GEMM, occupancy 2: B sub-tiled 32 cols ----------------
// C = A @ (Whi + Wlo/1024)^T, fp32 accumulate in two fragments, recombined at store.
// 8 warps = 4M x 2N, warp tile 32x16. ntiles counts 32-col tiles.
__global__ void __launch_bounds__(256, 2)
k_wgemm(const __half* __restrict__ A, const __half* __restrict__ Bhi,
        const __half* __restrict__ Blo, float* __restrict__ C,
        int M, int K, int ldC, int ntiles) {
    extern __shared__ char smem[];
    const int tid = threadIdx.x;
    const int blockRow = blockIdx.x * 128;
    const int ldS = K + 16;

    __half* As = (__half*)smem;               // [128][ldS]
    __half* Bh = As + 128 * ldS;              // [32][ldS]
    __half* Bl = Bh + 32 * ldS;

    // ---- copy A fp16 into padded SMEM (once) ----
    const int K8 = K >> 3;
    for (int idx = tid; idx < 128 * K8; idx += 256) {
        int r = idx / K8, c = (idx % K8) * 8;
        uint4 v = __ldg((const uint4*)(A + (size_t)(blockRow + r) * K + c));
        *(uint4*)(As + (size_t)r * ldS + c) = v;
    }

    const int warpId = tid >> 5;
    const int wm = warpId & 3;       // 4 M quadrants of 32 rows
    const int wn = warpId >> 2;      // 2 N halves of 16 cols
    const int row0 = wm * 32;
    const int col0 = wn * 16;

    for (int nt = 0; nt < ntiles; nt++) {
        const int n0 = nt * 32;
        __syncthreads();
        for (int idx = tid; idx < 32 * K8; idx += 256) {
            int n = idx / K8, c = (idx % K8) * 8;
            uint4 vh = __ldg((const uint4*)(Bhi + (size_t)(n0 + n) * K + c));
            uint4 vl = __ldg((const uint4*)(Blo + (size_t)(n0 + n) * K + c));
            *(uint4*)(Bh + (size_t)n * ldS + c) = vh;
            *(uint4*)(Bl + (size_t)n * ldS + c) = vl;
        }
        __syncthreads();

        wmma::fragment<wmma::accumulator, 16, 16, 16, float> acch[2], accl[2];
#pragma unroll
        for (int i = 0; i < 2; i++) {
            wmma::fill_fragment(acch[i], 0.0f);
            wmma::fill_fragment(accl[i], 0.0f);
        }

        for (int k0 = 0; k0 < K; k0 += 16) {
            wmma::fragment<wmma::matrix_a, 16, 16, 16, __half, wmma::row_major> a[2];
            wmma::fragment<wmma::matrix_b, 16, 16, 16, __half, wmma::col_major> bh, bl;
#pragma unroll
            for (int i = 0; i < 2; i++)
                wmma::load_matrix_sync(a[i], As + (size_t)(row0 + i * 16) * ldS + k0, ldS);
            wmma::load_matrix_sync(bh, Bh + (size_t)col0 * ldS + k0, ldS);
            wmma::load_matrix_sync(bl, Bl + (size_t)col0 * ldS + k0, ldS);
#pragma unroll
            for (int i = 0; i < 2; i++) {
                wmma::mma_sync(acch[i], a[i], bh, acch[i]);
                wmma::mma_sync(accl[i], a[i], bl, accl[i]);
            }
        }

#pragma unroll
        for (int i = 0; i < 2; i++) {
#pragma unroll
            for (int t = 0; t < acch[i].num_elements; t++)
                acch[i].x[t] += accl[i].x[t] * INV_LO;
            float* cp = C + (size_t)(blockRow + row0 + i * 16) * ldC + n0 + col0;
            wmma::store_matrix_sync(cp, acch[i], ldC, wmma::mem_row_major);
        }
    }
}

// ---------------- gates: z fp32, rh -> fp16 gather source ----------------
__global__ void k_gate(const float* __restrict__ hi,
                       const float* __restrict__ bxz, const float* __restrict__ bhz,
                       const float* __restrict__ bxr, const float* __restrict__ bhr, int n) {
    int idx = blockIdx.x * blockDim.x + threadIdx.x;
    if (idx >= n * 32) return;
    int m = idx >> 5, j = idx & 31;
    const float4* P4 = (const float4*)g_P;
    float4 pz = P4[(size_t)m * 96 + j];
    float4 pr = P4[(size_t)m * 96 + 32 + j];
    float4 b0 = __ldg((const float4*)bxz + j);
    float4 b1 = __ldg((const float4*)bhz + j);
    float4 b2 = __ldg((const float4*)bxr + j);
    float4 b3 = __ldg((const float4*)bhr + j);
    float4 hv = __ldg((const float4*)hi + (size_t)m * 32 + j);

    float4 z, rh;
    z.x = sigmoidf(pz.x + b0.x + b1.x); z.y = sigmoidf(pz.y + b0.y + b1.y);
    z.z = sigmoidf(pz.z + b0.z + b1.z); z.w = sigmoidf(pz.w + b0.w + b1.w);
    float rx = sigmoidf(pr.x + b2.x + b3.x), ry = sigmoidf(pr.y + b2.y + b3.y);
    float rz = sigmoidf(pr.z + b2.z + b3.z), rw = sigmoidf(pr.w + b2.w + b3.w);
    rh.x = rx * hv.x; rh.y = ry * hv.y; rh.z = rz * hv.z; rh.w = rw * hv.w;

    ((float4*)g_z)[(size_t)m * 32 + j] = z;
    __half2 p0 = __floats2half2_rn(rh.x, rh.y), p1 = __floats2half2_rn(rh.z, rh.w);
    uint2 packed;
    packed.x = *(uint32_t*)&p0; packed.y = *(uint32_t*)&p1;
    ((uint2*)g_rhh)[(size_t)m * 32 + j] = packed;
}

// ---------------- final: ho; optionally pack next layer's [ho|hnext] fp16 ----------------
__global__ void k_final(const float* __restrict__ hi,
                        const float* __restrict__ bxh, const float* __restrict__ bhh,
                        const float* __restrict__ hnext,
                        float* __restrict__ out, int n) {
    int idx = blockIdx.x * blockDim.x + threadIdx.x;
    if (idx >= n * 32) return;
    int m = idx >> 5, j = idx & 31;
    float4 pxh = ((const float4*)g_P)[(size_t)m * 96 + 64 + j];
    float4 q = ((const float4*)g_Q)[(size_t)m * 32 + j];
    float4 b0 = __ldg((const float4*)bxh + j);
    float4 b1 = __ldg((const float4*)bhh + j);
    float4 zv = ((const float4*)g_z)[(size_t)m * 32 + j];
    float4 hv = __ldg((const float4*)hi + (size_t)m * 32 + j);
    float4 ho;
    float ht;
    ht = tanhf(pxh.x + q.x + b0.x + b1.x); ho.x = zv.x * hv.x + (1.0f - zv.x) * ht;
    ht = tanhf(pxh.y + q.y + b0.y + b1.y); ho.y = zv.y * hv.y + (1.0f - zv.y) * ht;
    ht = tanhf(pxh.z + q.z + b0.z + b1.z); ho.z = zv.z * hv.z + (1.0f - zv.z) * ht;
    ht = tanhf(pxh.w + q.w + b0.w + b1.w); ho.w = zv.w * hv.w + (1.0f - zv.w) * ht;
    ((float4*)out)[(size_t)m * 32 + j] = ho;
    if (hnext) {
        __half2 x0 = __floats2half2_rn(ho.x, ho.y), x1 = __floats2half2_rn(ho.z, ho.w);
        uint2 px; px.x = *(uint32_t*)&x0; px.y = *(uint32_t*)&x1;
        ((uint2*)g_xhh)[(size_t)m * 64 + j] = px;                 // x-half
        float4 hn = __ldg((const float4*)hnext + (size_t)m * 32 + j);
        __half2 n0 = __floats2half2_rn(hn.x, hn.y), n1 = __floats2half2_rn(hn.z, hn.w);
        uint2 pn; pn.x = *(uint32_t*)&n0; pn.y = *(uint32_t*)&n1;
        ((uint2*)g_xhh)[(size_t)m * 64 + 32 + j] = pn;            // h-half
    }
}

// ---------------- host ----------------
extern "C" void kernel_launch(void* const* d_in, const int* in_sizes, int n_in,
                              void* d_out, int out_size) {
    const float* x   = (const float*)d_in[0];
    const int*   ei  = (const int*)d_in[1];
    const float* ew  = (const float*)d_in[2];
    const float* h   = (const float*)d_in[3];
    const float* Wxz = (const float*)d_in[4];  const float* bxz = (const float*)d_in[5];
    const float* Whz = (const float*)d_in[6];  const float* bhz = (const float*)d_in[7];
    const float* Wxr = (const float*)d_in[8];  const float* bxr = (const float*)d_in[9];
    const float* Whr = (const float*)d_in[10]; const float* bhr = (const float*)d_in[11];
    const float* Wxh = (const float*)d_in[12]; const float* bxh = (const float*)d_in[13];
    const float* Whh = (const float*)d_in[14]; const float* bhh = (const float*)d_in[15];
    float* out = (float*)d_out;

    int N = in_sizes[0] / D;
    int E = in_sizes[2];
    int L = in_sizes[5] / D;

    const int* rowi = ei;
    const int* coli = ei + E;

    float *p_P, *p_Q;
    __half *p_axh, *p_aSr, *p_w1h, *p_w1l, *p_w2h, *p_w2l;
    cudaGetSymbolAddress((void**)&p_axh, g_axh);
    cudaGetSymbolAddress((void**)&p_aSr, g_aSr);
    cudaGetSymbolAddress((void**)&p_P,   g_P);
    cudaGetSymbolAddress((void**)&p_Q,   g_Q);
    cudaGetSymbolAddress((void**)&p_w1h, g_W1h);
    cudaGetSymbolAddress((void**)&p_w1l, g_W1l);
    cudaGetSymbolAddress((void**)&p_w2h, g_W2h);
    cudaGetSymbolAddress((void**)&p_w2l, g_W2l);

    int smem1 = (128 + 32 + 32) * (256 + 16) * 2;  // K=256: 104,448 B -> occ 2
    int smem2 = (128 + 32 + 32) * (128 + 16) * 2;  // K=128: 55,296 B
    cudaFuncSetAttribute(k_wgemm, cudaFuncAttributeMaxDynamicSharedMemorySize, smem1);

    // ---- one-time: weight split (all layers), degrees, CSR build ----
    k_build_wt1<<<(L * 384 * 256 + 255) / 256, 256>>>(Wxz, Whz, Wxr, Whr, Wxh, L);
    k_build_wt2<<<(L * 128 * 128 + 255) / 256, 256>>>(Whh, L);
    k_deg_init<<<(N + 255) / 256, 256>>>(N);
    k_deg_edges<<<(E + 255) / 256, 256>>>(coli, ew, E);
    int nscan = (N + 1023) / 1024;
    k_scan1<<<nscan, 1024>>>(N);
    k_scan2<<<1, 64>>>(nscan);
    k_scan3<<<(N + 255) / 256, 256>>>(N);
    k_place<<<(E + 255) / 256, 256>>>(rowi, coli, ew, E);

    int nwblocks = (N * 32 + 255) / 256;  // warp per node
    int mtiles = (N + 127) / 128;

    k_prep<<<(N * 32 + 255) / 256, 256>>>(x, h, N);  // layer 0 pack only

    for (int i = 0; i < L; i++) {
        const float* hi = h + (size_t)i * N * D;
        const float* hnext = (i + 1 < L) ? h + (size_t)(i + 1) * N * D : nullptr;

        k_csr256<<<nwblocks, 256>>>(N);
        k_wgemm<<<mtiles, 256, smem1>>>(p_axh, p_w1h + (size_t)i * 384 * 256,
                                        p_w1l + (size_t)i * 384 * 256, p_P, N, 256, 384, 12);
        k_gate<<<(N * 32 + 255) / 256, 256>>>(hi, bxz + i * D, bhz + i * D, bxr + i * D, bhr + i * D, N);
        k_csr128<<<nwblocks, 256>>>(N);
        k_wgemm<<<mtiles, 256, smem2>>>(p_aSr, p_w2h + (size_t)i * 128 * 128,
                                        p_w2l + (size_t)i * 128 * 128, p_Q, N, 128, 128, 4);
        k_final<<<(N * 32 + 255) / 256, 256>>>(hi, bxh + i * D, bhh + i * D, hnext,
                                               out + (size_t)i * N * D, N);
    }
}

// round 11
// speedup vs baseline: 1.1188x; 1.1188x over previous
#include <cuda_runtime.h>
#include <cuda_fp16.h>
#include <mma.h>
#include <math.h>
#include <stdint.h>

using namespace nvcuda;

#define D 128
#define MAXN 50432
#define MAXE 1700000
#define LO_SCALE 1024.0f
#define INV_LO (1.0f / 1024.0f)

// ---------------- scratch (device globals: allocation-free) ----------------
__device__ float g_dinv[MAXN];                 // deg -> rsqrt(deg)
__device__ int   g_cnt[MAXN];                  // in-degree histogram
__device__ int   g_off[MAXN + 1];              // CSR offsets
__device__ int   g_cur[MAXN];                  // placement cursors
__device__ int   g_tmp[MAXN];                  // scan scratch
__device__ int   g_part[64];                   // scan block partials
__device__ int2  g_srt[MAXE];                  // packed (row, norm) per edge, grouped by col
__device__ __half g_xhh[(size_t)MAXN * 256];   // [x|h] fp16 gather source
__device__ __half g_rhh[(size_t)MAXN * D];     // r*h fp16 gather source
__device__ __half g_axh[(size_t)MAXN * 256];   // [S@x | S@h]  (GEMM1 A, fp16)
__device__ __half g_aSr[(size_t)MAXN * D];     // S@(r*h)      (GEMM2 A, fp16)
__device__ float g_P[(size_t)MAXN * 384];      // GEMM1 out: [z_pre | r_pre | xh_part]
__device__ float g_Q[(size_t)MAXN * D];        // GEMM2 out
__device__ float g_z[(size_t)MAXN * D];        // z gate
__device__ __half g_W1h[2 * 384 * 256];        // GEMM1 B hi (n-major, per layer)
__device__ __half g_W1l[2 * 384 * 256];        // GEMM1 B lo*1024
__device__ __half g_W2h[2 * 128 * 128];        // GEMM2 B hi
__device__ __half g_W2l[2 * 128 * 128];        // GEMM2 B lo*1024

__device__ __forceinline__ float sigmoidf(float x) { return 1.0f / (1.0f + expf(-x)); }

__device__ __forceinline__ uint32_t smem_u32(const void* p) {
    uint32_t a;
    asm("{ .reg .u64 t; cvta.to.shared.u64 t, %1; cvt.u32.u64 %0, t; }" : "=r"(a) : "l"(p));
    return a;
}
#define CP_ASYNC16(dst, src) \
    asm volatile("cp.async.ca.shared.global [%0], [%1], 16;" :: "r"(dst), "l"(src) : "memory")
#define CP_COMMIT() asm volatile("cp.async.commit_group;" ::: "memory")
#define CP_WAIT0()  asm volatile("cp.async.wait_group 0;" ::: "memory")
#define CP_WAIT1()  asm volatile("cp.async.wait_group 1;" ::: "memory")

// ---------------- degree / histogram ----------------
__global__ void k_deg_init(int n) {
    int i = blockIdx.x * blockDim.x + threadIdx.x;
    if (i < n) { g_dinv[i] = 1.0f; g_cnt[i] = 0; }
}
__global__ void k_deg_edges(const int* __restrict__ coli, const float* __restrict__ w, int E) {
    int e = blockIdx.x * blockDim.x + threadIdx.x;
    if (e < E) {
        int c = coli[e];
        atomicAdd(&g_dinv[c], w[e]);
        atomicAdd(&g_cnt[c], 1);
    }
}

// ---------------- multi-block scan (phase 1 also finalizes dinv) ----------------
__global__ void __launch_bounds__(1024)
k_scan1(int n) {
    __shared__ int warpsum[32];
    int i = blockIdx.x * 1024 + threadIdx.x;
    int lane = threadIdx.x & 31, wid = threadIdx.x >> 5;
    if (i < n) {
        float d = g_dinv[i];
        g_dinv[i] = (d > 0.0f) ? rsqrtf(d) : 0.0f;
    }
    int v = (i < n) ? g_cnt[i] : 0;
    int x = v;
#pragma unroll
    for (int o = 1; o < 32; o <<= 1) {
        int t = __shfl_up_sync(~0u, x, o);
        if (lane >= o) x += t;
    }
    if (lane == 31) warpsum[wid] = x;
    __syncthreads();
    if (wid == 0) {
        int s = warpsum[lane];
#pragma unroll
        for (int o = 1; o < 32; o <<= 1) {
            int t = __shfl_up_sync(~0u, s, o);
            if (lane >= o) s += t;
        }
        warpsum[lane] = s;
    }
    __syncthreads();
    int incl = x + ((wid > 0) ? warpsum[wid - 1] : 0);
    if (i < n) g_tmp[i] = incl;
    if (threadIdx.x == 1023) g_part[blockIdx.x] = incl;
}
__global__ void k_scan2(int nb) {
    __shared__ int sm[64];
    int t = threadIdx.x;
    sm[t] = (t < nb) ? g_part[t] : 0;
    __syncthreads();
    for (int o = 1; o < 64; o <<= 1) {
        int v = (t >= o) ? sm[t - o] : 0;
        __syncthreads();
        sm[t] += v;
        __syncthreads();
    }
    g_part[t] = (t > 0) ? sm[t - 1] : 0;
}
__global__ void k_scan3(int n) {
    int i = blockIdx.x * blockDim.x + threadIdx.x;
    if (i >= n) return;
    int off = g_tmp[i] + g_part[i >> 10];
    g_off[i + 1] = off;
    g_cur[i] = off - g_cnt[i];
    if (i == 0) g_off[0] = 0;
}

// ---------------- placement scatter ----------------
__global__ void k_place(const int* __restrict__ rowi, const int* __restrict__ coli,
                        const float* __restrict__ w, int E) {
    int e = blockIdx.x * blockDim.x + threadIdx.x;
    if (e >= E) return;
    int r = rowi[e], c = coli[e];
    float nrm = w[e] * __ldg(g_dinv + r) * __ldg(g_dinv + c);
    int pos = atomicAdd(&g_cur[c], 1);
    g_srt[pos] = make_int2(r, __float_as_int(nrm));
}

// ---------------- weight build: all layers, fp16 hi + scaled lo, n-major ----------------
__global__ void k_build_wt1(const float* __restrict__ Wxz, const float* __restrict__ Whz,
                            const float* __restrict__ Wxr, const float* __restrict__ Whr,
                            const float* __restrict__ Wxh, int L) {
    int idx = blockIdx.x * blockDim.x + threadIdx.x;
    if (idx >= L * 384 * 256) return;
    int layer = idx / (384 * 256);
    int rem = idx % (384 * 256);
    int n = rem / 256, k = rem % 256;
    int blk = n >> 7, nn = n & 127;
    size_t wo = (size_t)layer * D * D;
    float v;
    if (blk == 0)      v = (k < 128) ? Wxz[wo + k * 128 + nn] : Whz[wo + (k - 128) * 128 + nn];
    else if (blk == 1) v = (k < 128) ? Wxr[wo + k * 128 + nn] : Whr[wo + (k - 128) * 128 + nn];
    else               v = (k < 128) ? Wxh[wo + k * 128 + nn] : 0.0f;
    __half hi = __float2half_rn(v);
    g_W1h[idx] = hi;
    g_W1l[idx] = __float2half_rn((v - __half2float(hi)) * LO_SCALE);
}
__global__ void k_build_wt2(const float* __restrict__ Whh, int L) {
    int idx = blockIdx.x * blockDim.x + threadIdx.x;
    if (idx >= L * 128 * 128) return;
    int layer = idx / (128 * 128);
    int rem = idx % (128 * 128);
    int n = rem / 128, k = rem % 128;
    float v = Whh[(size_t)layer * D * D + k * 128 + n];
    __half hi = __float2half_rn(v);
    g_W2h[idx] = hi;
    g_W2l[idx] = __float2half_rn((v - __half2float(hi)) * LO_SCALE);
}

// ---------------- prep: pack [x|h] fp32 -> fp16 gather rows (layer 0 only) ----------------
__global__ void k_prep(const float* __restrict__ x, const float* __restrict__ h, int n) {
    int idx = blockIdx.x * blockDim.x + threadIdx.x;
    if (idx >= n * 32) return;
    int m = idx >> 5, j = idx & 31;
    const float4* src = (j < 16) ? (const float4*)x + (size_t)m * 32 + 2 * j
                                 : (const float4*)h + (size_t)m * 32 + 2 * (j - 16);
    float4 a = __ldg(src), b = __ldg(src + 1);
    __half2 h0 = __floats2half2_rn(a.x, a.y), h1 = __floats2half2_rn(a.z, a.w);
    __half2 h2 = __floats2half2_rn(b.x, b.y), h3 = __floats2half2_rn(b.z, b.w);
    uint4 o;
    o.x = *(uint32_t*)&h0; o.y = *(uint32_t*)&h1; o.z = *(uint32_t*)&h2; o.w = *(uint32_t*)&h3;
    ((uint4*)g_xhh)[(size_t)m * 32 + j] = o;
}

// ---------------- CSR gather: 256-wide fp16 -> g_axh fp16, warp per node ----------------
__global__ void __launch_bounds__(256)
k_csr256(int n) {
    int node = (blockIdx.x * blockDim.x + threadIdx.x) >> 5;
    if (node >= n) return;
    int lane = threadIdx.x & 31;
    const uint4* src = (const uint4*)g_xhh;
    float di = __ldg(g_dinv + node);
    float s = di * di;
    float acc[8];
    {
        uint4 v = __ldg(src + (size_t)node * 32 + lane);
        float2 f0 = __half22float2(*(__half2*)&v.x), f1 = __half22float2(*(__half2*)&v.y);
        float2 f2 = __half22float2(*(__half2*)&v.z), f3 = __half22float2(*(__half2*)&v.w);
        acc[0] = s * f0.x; acc[1] = s * f0.y; acc[2] = s * f1.x; acc[3] = s * f1.y;
        acc[4] = s * f2.x; acc[5] = s * f2.y; acc[6] = s * f3.x; acc[7] = s * f3.y;
    }
    int e0 = __ldg(g_off + node), e1 = __ldg(g_off + node + 1);
#pragma unroll 4
    for (int e = e0; e < e1; e++) {
        int2 p = __ldg(g_srt + e);
        float nrm = __int_as_float(p.y);
        uint4 v = __ldg(src + (size_t)p.x * 32 + lane);
        float2 f0 = __half22float2(*(__half2*)&v.x), f1 = __half22float2(*(__half2*)&v.y);
        float2 f2 = __half22float2(*(__half2*)&v.z), f3 = __half22float2(*(__half2*)&v.w);
        acc[0] += nrm * f0.x; acc[1] += nrm * f0.y; acc[2] += nrm * f1.x; acc[3] += nrm * f1.y;
        acc[4] += nrm * f2.x; acc[5] += nrm * f2.y; acc[6] += nrm * f3.x; acc[7] += nrm * f3.y;
    }
    __half2 o0 = __floats2half2_rn(acc[0], acc[1]), o1 = __floats2half2_rn(acc[2], acc[3]);
    __half2 o2 = __floats2half2_rn(acc[4], acc[5]), o3 = __floats2half2_rn(acc[6], acc[7]);
    uint4 o;
    o.x = *(uint32_t*)&o0; o.y = *(uint32_t*)&o1; o.z = *(uint32_t*)&o2; o.w = *(uint32_t*)&o3;
    ((uint4*)g_axh)[(size_t)node * 32 + lane] = o;
}

// ---------------- CSR gather: 128-wide fp16 (g_rhh -> g_aSr fp16), warp per node -------
__global__ void __launch_bounds__(256)
k_csr128(int n) {
    int node = (blockIdx.x * blockDim.x + threadIdx.x) >> 5;
    if (node >= n) return;
    int lane = threadIdx.x & 31;
    const uint2* src = (const uint2*)g_rhh;
    float di = __ldg(g_dinv + node);
    float s = di * di;
    float acc[4];
    {
        uint2 v = __ldg(src + (size_t)node * 32 + lane);
        float2 f0 = __half22float2(*(__half2*)&v.x), f1 = __half22float2(*(__half2*)&v.y);
        acc[0] = s * f0.x; acc[1] = s * f0.y; acc[2] = s * f1.x; acc[3] = s * f1.y;
    }
    int e0 = __ldg(g_off + node), e1 = __ldg(g_off + node + 1);
#pragma unroll 4
    for (int e = e0; e < e1; e++) {
        int2 p = __ldg(g_srt + e);
        float nrm = __int_as_float(p.y);
        uint2 v = __ldg(src + (size_t)p.x * 32 + lane);
        float2 f0 = __half22float2(*(__half2*)&v.x), f1 = __half22float2(*(__half2*)&v.y);
        acc[0] += nrm * f0.x; acc[1] += nrm * f0.y; acc[2] += nrm * f1.x; acc[3] += nrm * f1.y;
    }
    __half2 o0 = __floats2half2_rn(acc[0], acc[1]), o1 = __floats2half2_rn(acc[2], acc[3]);
    uint2 o;
    o.x = *(uint32_t*)&o0; o.y = *(uint32_t*)&o1;
    ((uint2*)g_aSr)[(size_t)node * 32 + lane] = o;
}

// ---------------- WMMA fp16 GEMM: 64-col tiles, double-buffered B via cp.async ----------
// C = A @ (Whi + Wlo/1024)^T, fp32 accumulate, 2 passes recombined at store.
// Tiles nt >= kredFrom run with K=128 (zero-padded W block skipped).
__global__ void __launch_bounds__(256, 1)
k_wgemm(const __half* __restrict__ A, const __half* __restrict__ Bhi,
        const __half* __restrict__ Blo, float* __restrict__ C,
        int M, int K, int ldC, int ntiles, int kredFrom) {
    extern __shared__ char smem[];
    const int tid = threadIdx.x;
    const int blockRow = blockIdx.x * 128;
    const int ldS = K + 16;

    __half* As = (__half*)smem;                       // [128][ldS]
    __half* Bbuf = As + 128 * ldS;                    // 2 x (Bh[64][ldS] + Bl[64][ldS])
    const size_t BSTRIDE = (size_t)2 * 64 * ldS;

    const int K8 = K >> 3;

    // prefetch B tile nt into buffer nt&1
    auto prefetchB = [&](int nt) {
        int b = nt & 1;
        __half* Bh = Bbuf + (size_t)b * BSTRIDE;
        __half* Bl = Bh + 64 * ldS;
        int ktile = (nt >= kredFrom) ? 128 : K;
        int kt8 = ktile >> 3;
        int n0 = nt * 64;
        for (int idx = tid; idx < 64 * kt8; idx += 256) {
            int n = idx / kt8, c = (idx % kt8) * 8;
            CP_ASYNC16(smem_u32(Bh + (size_t)n * ldS + c), Bhi + (size_t)(n0 + n) * K + c);
            CP_ASYNC16(smem_u32(Bl + (size_t)n * ldS + c), Blo + (size_t)(n0 + n) * K + c);
        }
        CP_COMMIT();
    };

    prefetchB(0);  // overlaps with A load below

    // ---- copy A fp16 into padded SMEM (once) ----
    for (int idx = tid; idx < 128 * K8; idx += 256) {
        int r = idx / K8, c = (idx % K8) * 8;
        uint4 v = __ldg((const uint4*)(A + (size_t)(blockRow + r) * K + c));
        *(uint4*)(As + (size_t)r * ldS + c) = v;
    }

    const int warpId = tid >> 5;
    const int wm = warpId & 3;
    const int wn = warpId >> 2;
    const int row0 = wm * 32;
    const int col0 = wn * 32;

    for (int nt = 0; nt < ntiles; nt++) {
        __syncthreads();   // prev MMA done reading buffer (nt+1)&1; A stores done (nt==0)
        if (nt + 1 < ntiles) {
            prefetchB(nt + 1);
            CP_WAIT1();    // tile nt landed; nt+1 still in flight
        } else {
            CP_WAIT0();
        }
        __syncthreads();   // tile nt visible to all warps

        int b = nt & 1;
        const __half* Bh = Bbuf + (size_t)b * BSTRIDE;
        const __half* Bl = Bh + 64 * ldS;
        const int n0 = nt * 64;
        const int ktile = (nt >= kredFrom) ? 128 : K;

        wmma::fragment<wmma::accumulator, 16, 16, 16, float> acch[2][2], accl[2][2];
#pragma unroll
        for (int i = 0; i < 2; i++)
#pragma unroll
            for (int j = 0; j < 2; j++) {
                wmma::fill_fragment(acch[i][j], 0.0f);
                wmma::fill_fragment(accl[i][j], 0.0f);
            }

        for (int k0 = 0; k0 < ktile; k0 += 16) {
            wmma::fragment<wmma::matrix_a, 16, 16, 16, __half, wmma::row_major> a[2];
            wmma::fragment<wmma::matrix_b, 16, 16, 16, __half, wmma::col_major> bh[2], bl[2];
#pragma unroll
            for (int i = 0; i < 2; i++)
                wmma::load_matrix_sync(a[i], As + (size_t)(row0 + i * 16) * ldS + k0, ldS);
#pragma unroll
            for (int j = 0; j < 2; j++) {
                wmma::load_matrix_sync(bh[j], Bh + (size_t)(col0 + j * 16) * ldS + k0, ldS);
                wmma::load_matrix_sync(bl[j], Bl + (size_t)(col0 + j * 16) * ldS + k0, ldS);
            }
#pragma unroll
            for (int i = 0; i < 2; i++)
#pragma unroll
                for (int j = 0; j < 2; j++) {
                    wmma::mma_sync(acch[i][j], a[i], bh[j], acch[i][j]);
                    wmma::mma_sync(accl[i][j], a[i], bl[j], accl[i][j]);
                }
        }

#pragma unroll
        for (int i = 0; i < 2; i++)
#pragma unroll
            for (int j = 0; j < 2; j++) {
#pragma unroll
                for (int t = 0; t < acch[i][j].num_elements; t++)
                    acch[i][j].x[t] += accl[i][j].x[t] * INV_LO;
                float* cp = C + (size_t)(blockRow + row0 + i * 16) * ldC + n0 + col0 + j * 16;
                wmma::store_matrix_sync(cp, acch[i][j], ldC, wmma::mem_row_major);
            }
    }
}

// ---------------- gates: z fp32, rh -> fp16 gather source ----------------
__global__ void k_gate(const float* __restrict__ hi,
                       const float* __restrict__ bxz, const float* __restrict__ bhz,
                       const float* __restrict__ bxr, const float* __restrict__ bhr, int n) {
    int idx = blockIdx.x * blockDim.x + threadIdx.x;
    if (idx >= n * 32) return;
    int m = idx >> 5, j = idx & 31;
    const float4* P4 = (const float4*)g_P;
    float4 pz = P4[(size_t)m * 96 + j];
    float4 pr = P4[(size_t)m * 96 + 32 + j];
    float4 b0 = __ldg((const float4*)bxz + j);
    float4 b1 = __ldg((const float4*)bhz + j);
    float4 b2 = __ldg((const float4*)bxr + j);
    float4 b3 = __ldg((const float4*)bhr + j);
    float4 hv = __ldg((const float4*)hi + (size_t)m * 32 + j);

    float4 z, rh;
    z.x = sigmoidf(pz.x + b0.x + b1.x); z.y = sigmoidf(pz.y + b0.y + b1.y);
    z.z = sigmoidf(pz.z + b0.z + b1.z); z.w = sigmoidf(pz.w + b0.w + b1.w);
    float rx = sigmoidf(pr.x + b2.x + b3.x), ry = sigmoidf(pr.y + b2.y + b3.y);
    float rz = sigmoidf(pr.z + b2.z + b3.z), rw = sigmoidf(pr.w + b2.w + b3.w);
    rh.x = rx * hv.x; rh.y = ry * hv.y; rh.z = rz * hv.z; rh.w = rw * hv.w;

    ((float4*)g_z)[(size_t)m * 32 + j] = z;
    __half2 p0 = __floats2half2_rn(rh.x, rh.y), p1 = __floats2half2_rn(rh.z, rh.w);
    uint2 packed;
    packed.x = *(uint32_t*)&p0; packed.y = *(uint32_t*)&p1;
    ((uint2*)g_rhh)[(size_t)m * 32 + j] = packed;
}

// ---------------- final: ho; optionally pack next layer's [ho|hnext] fp16 ----------------
__global__ void k_final(const float* __restrict__ hi,
                        const float* __restrict__ bxh, const float* __restrict__ bhh,
                        const float* __restrict__ hnext,
                        float* __restrict__ out, int n) {
    int idx = blockIdx.x * blockDim.x + threadIdx.x;
    if (idx >= n * 32) return;
    int m = idx >> 5, j = idx & 31;
    float4 pxh = ((const float4*)g_P)[(size_t)m * 96 + 64 + j];
    float4 q = ((const float4*)g_Q)[(size_t)m * 32 + j];
    float4 b0 = __ldg((const float4*)bxh + j);
    float4 b1 = __ldg((const float4*)bhh + j);
    float4 zv = ((const float4*)g_z)[(size_t)m * 32 + j];
    float4 hv = __ldg((const float4*)hi + (size_t)m * 32 + j);
    float4 ho;
    float ht;
    ht = tanhf(pxh.x + q.x + b0.x + b1.x); ho.x = zv.x * hv.x + (1.0f - zv.x) * ht;
    ht = tanhf(pxh.y + q.y + b0.y + b1.y); ho.y = zv.y * hv.y + (1.0f - zv.y) * ht;
    ht = tanhf(pxh.z + q.z + b0.z + b1.z); ho.z = zv.z * hv.z + (1.0f - zv.z) * ht;
    ht = tanhf(pxh.w + q.w + b0.w + b1.w); ho.w = zv.w * hv.w + (1.0f - zv.w) * ht;
    ((float4*)out)[(size_t)m * 32 + j] = ho;
    if (hnext) {
        __half2 x0 = __floats2half2_rn(ho.x, ho.y), x1 = __floats2half2_rn(ho.z, ho.w);
        uint2 px; px.x = *(uint32_t*)&x0; px.y = *(uint32_t*)&x1;
        ((uint2*)g_xhh)[(size_t)m * 64 + j] = px;                 // x-half
        float4 hn = __ldg((const float4*)hnext + (size_t)m * 32 + j);
        __half2 n0 = __floats2half2_rn(hn.x, hn.y), n1 = __floats2half2_rn(hn.z, hn.w);
        uint2 pn; pn.x = *(uint32_t*)&n0; pn.y = *(uint32_t*)&n1;
        ((uint2*)g_xhh)[(size_t)m * 64 + 32 + j] = pn;            // h-half
    }
}

// ---------------- host ----------------
extern "C" void kernel_launch(void* const* d_in, const int* in_sizes, int n_in,
                              void* d_out, int out_size) {
    const float* x   = (const float*)d_in[0];
    const int*   ei  = (const int*)d_in[1];
    const float* ew  = (const float*)d_in[2];
    const float* h   = (const float*)d_in[3];
    const float* Wxz = (const float*)d_in[4];  const float* bxz = (const float*)d_in[5];
    const float* Whz = (const float*)d_in[6];  const float* bhz = (const float*)d_in[7];
    const float* Wxr = (const float*)d_in[8];  const float* bxr = (const float*)d_in[9];
    const float* Whr = (const float*)d_in[10]; const float* bhr = (const float*)d_in[11];
    const float* Wxh = (const float*)d_in[12]; const float* bxh = (const float*)d_in[13];
    const float* Whh = (const float*)d_in[14]; const float* bhh = (const float*)d_in[15];
    float* out = (float*)d_out;

    int N = in_sizes[0] / D;
    int E = in_sizes[2];
    int L = in_sizes[5] / D;

    const int* rowi = ei;
    const int* coli = ei + E;

    float *p_P, *p_Q;
    __half *p_axh, *p_aSr, *p_w1h, *p_w1l, *p_w2h, *p_w2l;
    cudaGetSymbolAddress((void**)&p_axh, g_axh);
    cudaGetSymbolAddress((void**)&p_aSr, g_aSr);
    cudaGetSymbolAddress((void**)&p_P,   g_P);
    cudaGetSymbolAddress((void**)&p_Q,   g_Q);
    cudaGetSymbolAddress((void**)&p_w1h, g_W1h);
    cudaGetSymbolAddress((void**)&p_w1l, g_W1l);
    cudaGetSymbolAddress((void**)&p_w2h, g_W2h);
    cudaGetSymbolAddress((void**)&p_w2l, g_W2l);

    // A[128][K+16] + 2 x (Bh+Bl)[64][K+16] halves
    int smem1 = (128 * (256 + 16) + 2 * 2 * 64 * (256 + 16)) * 2;  // 208,896 B
    int smem2 = (128 * (128 + 16) + 2 * 2 * 64 * (128 + 16)) * 2;  // 110,592 B
    cudaFuncSetAttribute(k_wgemm, cudaFuncAttributeMaxDynamicSharedMemorySize, smem1);

    // ---- one-time: weight split (all layers), degrees, CSR build ----
    k_build_wt1<<<(L * 384 * 256 + 255) / 256, 256>>>(Wxz, Whz, Wxr, Whr, Wxh, L);
    k_build_wt2<<<(L * 128 * 128 + 255) / 256, 256>>>(Whh, L);
    k_deg_init<<<(N + 255) / 256, 256>>>(N);
    k_deg_edges<<<(E + 255) / 256, 256>>>(coli, ew, E);
    int nscan = (N + 1023) / 1024;
    k_scan1<<<nscan, 1024>>>(N);
    k_scan2<<<1, 64>>>(nscan);
    k_scan3<<<(N + 255) / 256, 256>>>(N);
    k_place<<<(E + 255) / 256, 256>>>(rowi, coli, ew, E);

    int nwblocks = (N * 32 + 255) / 256;  // warp per node
    int mtiles = (N + 127) / 128;

    k_prep<<<(N * 32 + 255) / 256, 256>>>(x, h, N);  // layer 0 pack only

    for (int i = 0; i < L; i++) {
        const float* hi = h + (size_t)i * N * D;
        const float* hnext = (i + 1 < L) ? h + (size_t)(i + 1) * N * D : nullptr;

        k_csr256<<<nwblocks, 256>>>(N);
        k_wgemm<<<mtiles, 256, smem1>>>(p_axh, p_w1h + (size_t)i * 384 * 256,
                                        p_w1l + (size_t)i * 384 * 256, p_P, N, 256, 384, 6, 4);
        k_gate<<<(N * 32 + 255) / 256, 256>>>(hi, bxz + i * D, bhz + i * D, bxr + i * D, bhr + i * D, N);
        k_csr128<<<nwblocks, 256>>>(N);
        k_wgemm<<<mtiles, 256, smem2>>>(p_aSr, p_w2h + (size_t)i * 128 * 128,
                                        p_w2l + (size_t)i * 128 * 128, p_Q, N, 128, 128, 2, 99);
        k_final<<<(N * 32 + 255) / 256, 256>>>(hi, bxh + i * D, bhh + i * D, hnext,
                                               out + (size_t)i * N * D, N);
    }
}

// round 12
// speedup vs baseline: 1.1685x; 1.0444x over previous
#include <cuda_runtime.h>
#include <cuda_fp16.h>
#include <mma.h>
#include <math.h>
#include <stdint.h>

using namespace nvcuda;

#define D 128
#define MAXN 50432
#define MAXE 1700000
#define LO_SCALE 1024.0f
#define INV_LO (1.0f / 1024.0f)
#define WFIX 1048576.0f      // 2^20 fixed-point for edge-weight sums
#define INV_WFIX (1.0f / 1048576.0f)

// ---------------- scratch (device globals: allocation-free) ----------------
__device__ float g_dinv[MAXN];                 // deg -> rsqrt(deg)
__device__ unsigned long long g_degpack[MAXN]; // (count << 32) | fixedpoint(sum w)
__device__ int   g_cnt[MAXN];                  // in-degree (unpacked)
__device__ int   g_off[MAXN + 1];              // CSR offsets
__device__ int   g_cur[MAXN];                  // placement cursors
__device__ int   g_tmp[MAXN];                  // scan scratch
__device__ int   g_part[64];                   // scan block partials
__device__ int2  g_srt[MAXE];                  // packed (row, norm) per edge, grouped by col
__device__ __half g_xhh[(size_t)MAXN * 256];   // [x|h] fp16 gather source
__device__ __half g_rhh[(size_t)MAXN * D];     // r*h fp16 gather source
__device__ __half g_axh[(size_t)MAXN * 256];   // [S@x | S@h]  (GEMM1 A, fp16)
__device__ __half g_aSr[(size_t)MAXN * D];     // S@(r*h)      (GEMM2 A, fp16)
__device__ __half g_P[(size_t)MAXN * 384];     // GEMM1 out (fp16): [z_pre | r_pre | xh_part]
__device__ __half g_Q[(size_t)MAXN * D];       // GEMM2 out (fp16)
__device__ __half g_z[(size_t)MAXN * D];       // z gate (fp16)
__device__ __half g_W1h[2 * 384 * 256];        // GEMM1 B hi (n-major, per layer)
__device__ __half g_W1l[2 * 384 * 256];        // GEMM1 B lo*1024
__device__ __half g_W2h[2 * 128 * 128];        // GEMM2 B hi
__device__ __half g_W2l[2 * 128 * 128];        // GEMM2 B lo*1024

__device__ __forceinline__ float sigmoidf(float x) { return 1.0f / (1.0f + expf(-x)); }

__device__ __forceinline__ uint32_t smem_u32(const void* p) {
    uint32_t a;
    asm("{ .reg .u64 t; cvta.to.shared.u64 t, %1; cvt.u32.u64 %0, t; }" : "=r"(a) : "l"(p));
    return a;
}
#define CP_ASYNC16(dst, src) \
    asm volatile("cp.async.ca.shared.global [%0], [%1], 16;" :: "r"(dst), "l"(src) : "memory")
#define CP_COMMIT() asm volatile("cp.async.commit_group;" ::: "memory")
#define CP_WAIT0()  asm volatile("cp.async.wait_group 0;" ::: "memory")
#define CP_WAIT1()  asm volatile("cp.async.wait_group 1;" ::: "memory")

// ---------------- degree / histogram (single packed atomic per edge) ----------------
__global__ void k_deg_init(int n) {
    int i = blockIdx.x * blockDim.x + threadIdx.x;
    if (i < n) g_degpack[i] = 0ULL;
}
__global__ void k_deg_edges(const int* __restrict__ coli, const float* __restrict__ w, int E) {
    int e = blockIdx.x * blockDim.x + threadIdx.x;
    if (e < E) {
        unsigned long long pk = (1ULL << 32) |
            (unsigned long long)(unsigned)__float2uint_rn(w[e] * WFIX);
        atomicAdd(&g_degpack[coli[e]], pk);
    }
}

// ---------------- multi-block scan (phase 1 unpacks degpack, finalizes dinv) ----------
__global__ void __launch_bounds__(1024)
k_scan1(int n) {
    __shared__ int warpsum[32];
    int i = blockIdx.x * 1024 + threadIdx.x;
    int lane = threadIdx.x & 31, wid = threadIdx.x >> 5;
    int v = 0;
    if (i < n) {
        unsigned long long pk = g_degpack[i];
        v = (int)(pk >> 32);
        float deg = (float)(unsigned)(pk & 0xffffffffULL) * INV_WFIX + 1.0f;  // + self loop
        g_dinv[i] = rsqrtf(deg);
        g_cnt[i] = v;
    }
    int x = v;
#pragma unroll
    for (int o = 1; o < 32; o <<= 1) {
        int t = __shfl_up_sync(~0u, x, o);
        if (lane >= o) x += t;
    }
    if (lane == 31) warpsum[wid] = x;
    __syncthreads();
    if (wid == 0) {
        int s = warpsum[lane];
#pragma unroll
        for (int o = 1; o < 32; o <<= 1) {
            int t = __shfl_up_sync(~0u, s, o);
            if (lane >= o) s += t;
        }
        warpsum[lane] = s;
    }
    __syncthreads();
    int incl = x + ((wid > 0) ? warpsum[wid - 1] : 0);
    if (i < n) g_tmp[i] = incl;
    if (threadIdx.x == 1023) g_part[blockIdx.x] = incl;
}
__global__ void k_scan2(int nb) {
    __shared__ int sm[64];
    int t = threadIdx.x;
    sm[t] = (t < nb) ? g_part[t] : 0;
    __syncthreads();
    for (int o = 1; o < 64; o <<= 1) {
        int v = (t >= o) ? sm[t - o] : 0;
        __syncthreads();
        sm[t] += v;
        __syncthreads();
    }
    g_part[t] = (t > 0) ? sm[t - 1] : 0;
}
__global__ void k_scan3(int n) {
    int i = blockIdx.x * blockDim.x + threadIdx.x;
    if (i >= n) return;
    int off = g_tmp[i] + g_part[i >> 10];
    g_off[i + 1] = off;
    g_cur[i] = off - g_cnt[i];
    if (i == 0) g_off[0] = 0;
}

// ---------------- placement scatter ----------------
__global__ void k_place(const int* __restrict__ rowi, const int* __restrict__ coli,
                        const float* __restrict__ w, int E) {
    int e = blockIdx.x * blockDim.x + threadIdx.x;
    if (e >= E) return;
    int r = rowi[e], c = coli[e];
    float nrm = w[e] * __ldg(g_dinv + r) * __ldg(g_dinv + c);
    int pos = atomicAdd(&g_cur[c], 1);
    g_srt[pos] = make_int2(r, __float_as_int(nrm));
}

// ---------------- weight build: all layers, fp16 hi + scaled lo, n-major ----------------
__global__ void k_build_wt1(const float* __restrict__ Wxz, const float* __restrict__ Whz,
                            const float* __restrict__ Wxr, const float* __restrict__ Whr,
                            const float* __restrict__ Wxh, int L) {
    int idx = blockIdx.x * blockDim.x + threadIdx.x;
    if (idx >= L * 384 * 256) return;
    int layer = idx / (384 * 256);
    int rem = idx % (384 * 256);
    int n = rem / 256, k = rem % 256;
    int blk = n >> 7, nn = n & 127;
    size_t wo = (size_t)layer * D * D;
    float v;
    if (blk == 0)      v = (k < 128) ? Wxz[wo + k * 128 + nn] : Whz[wo + (k - 128) * 128 + nn];
    else if (blk == 1) v = (k < 128) ? Wxr[wo + k * 128 + nn] : Whr[wo + (k - 128) * 128 + nn];
    else               v = (k < 128) ? Wxh[wo + k * 128 + nn] : 0.0f;
    __half hi = __float2half_rn(v);
    g_W1h[idx] = hi;
    g_W1l[idx] = __float2half_rn((v - __half2float(hi)) * LO_SCALE);
}
__global__ void k_build_wt2(const float* __restrict__ Whh, int L) {
    int idx = blockIdx.x * blockDim.x + threadIdx.x;
    if (idx >= L * 128 * 128) return;
    int layer = idx / (128 * 128);
    int rem = idx % (128 * 128);
    int n = rem / 128, k = rem % 128;
    float v = Whh[(size_t)layer * D * D + k * 128 + n];
    __half hi = __float2half_rn(v);
    g_W2h[idx] = hi;
    g_W2l[idx] = __float2half_rn((v - __half2float(hi)) * LO_SCALE);
}

// ---------------- prep: pack [x|h] fp32 -> fp16 gather rows (layer 0 only) ----------------
__global__ void k_prep(const float* __restrict__ x, const float* __restrict__ h, int n) {
    int idx = blockIdx.x * blockDim.x + threadIdx.x;
    if (idx >= n * 32) return;
    int m = idx >> 5, j = idx & 31;
    const float4* src = (j < 16) ? (const float4*)x + (size_t)m * 32 + 2 * j
                                 : (const float4*)h + (size_t)m * 32 + 2 * (j - 16);
    float4 a = __ldg(src), b = __ldg(src + 1);
    __half2 h0 = __floats2half2_rn(a.x, a.y), h1 = __floats2half2_rn(a.z, a.w);
    __half2 h2 = __floats2half2_rn(b.x, b.y), h3 = __floats2half2_rn(b.z, b.w);
    uint4 o;
    o.x = *(uint32_t*)&h0; o.y = *(uint32_t*)&h1; o.z = *(uint32_t*)&h2; o.w = *(uint32_t*)&h3;
    ((uint4*)g_xhh)[(size_t)m * 32 + j] = o;
}

// ---------------- CSR gather: 256-wide fp16 -> g_axh fp16, warp per node ----------------
__global__ void __launch_bounds__(256)
k_csr256(int n) {
    int node = (blockIdx.x * blockDim.x + threadIdx.x) >> 5;
    if (node >= n) return;
    int lane = threadIdx.x & 31;
    const uint4* src = (const uint4*)g_xhh;
    float di = __ldg(g_dinv + node);
    float s = di * di;
    float acc[8];
    {
        uint4 v = __ldg(src + (size_t)node * 32 + lane);
        float2 f0 = __half22float2(*(__half2*)&v.x), f1 = __half22float2(*(__half2*)&v.y);
        float2 f2 = __half22float2(*(__half2*)&v.z), f3 = __half22float2(*(__half2*)&v.w);
        acc[0] = s * f0.x; acc[1] = s * f0.y; acc[2] = s * f1.x; acc[3] = s * f1.y;
        acc[4] = s * f2.x; acc[5] = s * f2.y; acc[6] = s * f3.x; acc[7] = s * f3.y;
    }
    int e0 = __ldg(g_off + node), e1 = __ldg(g_off + node + 1);
#pragma unroll 4
    for (int e = e0; e < e1; e++) {
        int2 p = __ldg(g_srt + e);
        float nrm = __int_as_float(p.y);
        uint4 v = __ldg(src + (size_t)p.x * 32 + lane);
        float2 f0 = __half22float2(*(__half2*)&v.x), f1 = __half22float2(*(__half2*)&v.y);
        float2 f2 = __half22float2(*(__half2*)&v.z), f3 = __half22float2(*(__half2*)&v.w);
        acc[0] += nrm * f0.x; acc[1] += nrm * f0.y; acc[2] += nrm * f1.x; acc[3] += nrm * f1.y;
        acc[4] += nrm * f2.x; acc[5] += nrm * f2.y; acc[6] += nrm * f3.x; acc[7] += nrm * f3.y;
    }
    __half2 o0 = __floats2half2_rn(acc[0], acc[1]), o1 = __floats2half2_rn(acc[2], acc[3]);
    __half2 o2 = __floats2half2_rn(acc[4], acc[5]), o3 = __floats2half2_rn(acc[6], acc[7]);
    uint4 o;
    o.x = *(uint32_t*)&o0; o.y = *(uint32_t*)&o1; o.z = *(uint32_t*)&o2; o.w = *(uint32_t*)&o3;
    ((uint4*)g_axh)[(size_t)node * 32 + lane] = o;
}

// ---------------- CSR gather: 128-wide fp16 (g_rhh -> g_aSr fp16), warp per node -------
__global__ void __launch_bounds__(256)
k_csr128(int n) {
    int node = (blockIdx.x * blockDim.x + threadIdx.x) >> 5;
    if (node >= n) return;
    int lane = threadIdx.x & 31;
    const uint2* src = (const uint2*)g_rhh;
    float di = __ldg(g_dinv + node);
    float s = di * di;
    float acc[4];
    {
        uint2 v = __ldg(src + (size_t)node * 32 + lane);
        float2 f0 = __half22float2(*(__half2*)&v.x), f1 = __half22float2(*(__half2*)&v.y);
        acc[0] = s * f0.x; acc[1] = s * f0.y; acc[2] = s * f1.x; acc[3] = s * f1.y;
    }
    int e0 = __ldg(g_off + node), e1 = __ldg(g_off + node + 1);
#pragma unroll 4
    for (int e = e0; e < e1; e++) {
        int2 p = __ldg(g_srt + e);
        float nrm = __int_as_float(p.y);
        uint2 v = __ldg(src + (size_t)p.x * 32 + lane);
        float2 f0 = __half22float2(*(__half2*)&v.x), f1 = __half22float2(*(__half2*)&v.y);
        acc[0] += nrm * f0.x; acc[1] += nrm * f0.y; acc[2] += nrm * f1.x; acc[3] += nrm * f1.y;
    }
    __half2 o0 = __floats2half2_rn(acc[0], acc[1]), o1 = __floats2half2_rn(acc[2], acc[3]);
    uint2 o;
    o.x = *(uint32_t*)&o0; o.y = *(uint32_t*)&o1;
    ((uint2*)g_aSr)[(size_t)node * 32 + lane] = o;
}

// ---------------- WMMA fp16 GEMM: 64-col tiles, cp.async double-buffered B,
//                  fp16 C via SMEM staging in the just-consumed B buffer ----------------
__global__ void __launch_bounds__(256, 1)
k_wgemm(const __half* __restrict__ A, const __half* __restrict__ Bhi,
        const __half* __restrict__ Blo, __half* __restrict__ C,
        int M, int K, int ldC, int ntiles, int kredFrom) {
    extern __shared__ char smem[];
    const int tid = threadIdx.x;
    const int blockRow = blockIdx.x * 128;
    const int ldS = K + 16;

    __half* As = (__half*)smem;                       // [128][ldS]
    __half* Bbuf = As + 128 * ldS;                    // 2 x (Bh[64][ldS] + Bl[64][ldS])
    const size_t BSTRIDE = (size_t)2 * 64 * ldS;

    const int K8 = K >> 3;

    auto prefetchB = [&](int nt) {
        int b = nt & 1;
        __half* Bh = Bbuf + (size_t)b * BSTRIDE;
        __half* Bl = Bh + 64 * ldS;
        int ktile = (nt >= kredFrom) ? 128 : K;
        int kt8 = ktile >> 3;
        int n0 = nt * 64;
        for (int idx = tid; idx < 64 * kt8; idx += 256) {
            int n = idx / kt8, c = (idx % kt8) * 8;
            CP_ASYNC16(smem_u32(Bh + (size_t)n * ldS + c), Bhi + (size_t)(n0 + n) * K + c);
            CP_ASYNC16(smem_u32(Bl + (size_t)n * ldS + c), Blo + (size_t)(n0 + n) * K + c);
        }
        CP_COMMIT();
    };

    prefetchB(0);

    for (int idx = tid; idx < 128 * K8; idx += 256) {
        int r = idx / K8, c = (idx % K8) * 8;
        uint4 v = __ldg((const uint4*)(A + (size_t)(blockRow + r) * K + c));
        *(uint4*)(As + (size_t)r * ldS + c) = v;
    }

    const int warpId = tid >> 5;
    const int wm = warpId & 3;
    const int wn = warpId >> 2;
    const int row0 = wm * 32;
    const int col0 = wn * 32;

    for (int nt = 0; nt < ntiles; nt++) {
        __syncthreads();   // prev staging reads done; A stores done (nt==0)
        if (nt + 1 < ntiles) {
            prefetchB(nt + 1);
            CP_WAIT1();
        } else {
            CP_WAIT0();
        }
        __syncthreads();   // tile nt visible

        int b = nt & 1;
        const __half* Bh = Bbuf + (size_t)b * BSTRIDE;
        const __half* Bl = Bh + 64 * ldS;
        const int n0 = nt * 64;
        const int ktile = (nt >= kredFrom) ? 128 : K;

        wmma::fragment<wmma::accumulator, 16, 16, 16, float> acch[2][2], accl[2][2];
#pragma unroll
        for (int i = 0; i < 2; i++)
#pragma unroll
            for (int j = 0; j < 2; j++) {
                wmma::fill_fragment(acch[i][j], 0.0f);
                wmma::fill_fragment(accl[i][j], 0.0f);
            }

        for (int k0 = 0; k0 < ktile; k0 += 16) {
            wmma::fragment<wmma::matrix_a, 16, 16, 16, __half, wmma::row_major> a[2];
            wmma::fragment<wmma::matrix_b, 16, 16, 16, __half, wmma::col_major> bh[2], bl[2];
#pragma unroll
            for (int i = 0; i < 2; i++)
                wmma::load_matrix_sync(a[i], As + (size_t)(row0 + i * 16) * ldS + k0, ldS);
#pragma unroll
            for (int j = 0; j < 2; j++) {
                wmma::load_matrix_sync(bh[j], Bh + (size_t)(col0 + j * 16) * ldS + k0, ldS);
                wmma::load_matrix_sync(bl[j], Bl + (size_t)(col0 + j * 16) * ldS + k0, ldS);
            }
#pragma unroll
            for (int i = 0; i < 2; i++)
#pragma unroll
                for (int j = 0; j < 2; j++) {
                    wmma::mma_sync(acch[i][j], a[i], bh[j], acch[i][j]);
                    wmma::mma_sync(accl[i][j], a[i], bl[j], accl[i][j]);
                }
        }

        // ---- stage fp32 tile into the just-consumed B buffer, convert to fp16 C ----
        __syncthreads();   // all warps finished reading Bh/Bl of buffer b
        float* stage = (float*)(Bbuf + (size_t)b * BSTRIDE);
        const int ldSt = 68;
#pragma unroll
        for (int i = 0; i < 2; i++)
#pragma unroll
            for (int j = 0; j < 2; j++) {
#pragma unroll
                for (int t = 0; t < acch[i][j].num_elements; t++)
                    acch[i][j].x[t] += accl[i][j].x[t] * INV_LO;
                wmma::store_matrix_sync(stage + (size_t)(row0 + i * 16) * ldSt + col0 + j * 16,
                                        acch[i][j], ldSt, wmma::mem_row_major);
            }
        __syncthreads();
        for (int g = tid; g < 128 * 32; g += 256) {
            int r = g >> 5, c2 = (g & 31) * 2;
            float2 v = *(float2*)(stage + (size_t)r * ldSt + c2);
            __half2 hv = __floats2half2_rn(v.x, v.y);
            *(uint32_t*)(C + (size_t)(blockRow + r) * ldC + n0 + c2) = *(uint32_t*)&hv;
        }
    }
}

// ---------------- gates: z (fp16), rh -> fp16 gather source ----------------
__global__ void k_gate(const float* __restrict__ hi,
                       const float* __restrict__ bxz, const float* __restrict__ bhz,
                       const float* __restrict__ bxr, const float* __restrict__ bhr, int n) {
    int idx = blockIdx.x * blockDim.x + threadIdx.x;
    if (idx >= n * 32) return;
    int m = idx >> 5, j = idx & 31;
    const uint2* P2 = (const uint2*)g_P;      // 4 halves per uint2, row = 96 uint2
    uint2 pzu = P2[(size_t)m * 96 + j];
    uint2 pru = P2[(size_t)m * 96 + 32 + j];
    float2 pz01 = __half22float2(*(__half2*)&pzu.x), pz23 = __half22float2(*(__half2*)&pzu.y);
    float2 pr01 = __half22float2(*(__half2*)&pru.x), pr23 = __half22float2(*(__half2*)&pru.y);
    float4 b0 = __ldg((const float4*)bxz + j);
    float4 b1 = __ldg((const float4*)bhz + j);
    float4 b2 = __ldg((const float4*)bxr + j);
    float4 b3 = __ldg((const float4*)bhr + j);
    float4 hv = __ldg((const float4*)hi + (size_t)m * 32 + j);

    float z0 = sigmoidf(pz01.x + b0.x + b1.x), z1 = sigmoidf(pz01.y + b0.y + b1.y);
    float z2 = sigmoidf(pz23.x + b0.z + b1.z), z3 = sigmoidf(pz23.y + b0.w + b1.w);
    float r0 = sigmoidf(pr01.x + b2.x + b3.x), r1 = sigmoidf(pr01.y + b2.y + b3.y);
    float r2 = sigmoidf(pr23.x + b2.z + b3.z), r3 = sigmoidf(pr23.y + b2.w + b3.w);

    __half2 zo0 = __floats2half2_rn(z0, z1), zo1 = __floats2half2_rn(z2, z3);
    uint2 zo; zo.x = *(uint32_t*)&zo0; zo.y = *(uint32_t*)&zo1;
    ((uint2*)g_z)[(size_t)m * 32 + j] = zo;

    __half2 p0 = __floats2half2_rn(r0 * hv.x, r1 * hv.y);
    __half2 p1 = __floats2half2_rn(r2 * hv.z, r3 * hv.w);
    uint2 packed; packed.x = *(uint32_t*)&p0; packed.y = *(uint32_t*)&p1;
    ((uint2*)g_rhh)[(size_t)m * 32 + j] = packed;
}

// ---------------- final: ho; optionally pack next layer's [ho|hnext] fp16 ----------------
__global__ void k_final(const float* __restrict__ hi,
                        const float* __restrict__ bxh, const float* __restrict__ bhh,
                        const float* __restrict__ hnext,
                        float* __restrict__ out, int n) {
    int idx = blockIdx.x * blockDim.x + threadIdx.x;
    if (idx >= n * 32) return;
    int m = idx >> 5, j = idx & 31;
    uint2 pxu = ((const uint2*)g_P)[(size_t)m * 96 + 64 + j];
    uint2 qu  = ((const uint2*)g_Q)[(size_t)m * 32 + j];
    uint2 zu  = ((const uint2*)g_z)[(size_t)m * 32 + j];
    float2 px01 = __half22float2(*(__half2*)&pxu.x), px23 = __half22float2(*(__half2*)&pxu.y);
    float2 q01  = __half22float2(*(__half2*)&qu.x),  q23  = __half22float2(*(__half2*)&qu.y);
    float2 z01  = __half22float2(*(__half2*)&zu.x),  z23  = __half22float2(*(__half2*)&zu.y);
    float4 b0 = __ldg((const float4*)bxh + j);
    float4 b1 = __ldg((const float4*)bhh + j);
    float4 hv = __ldg((const float4*)hi + (size_t)m * 32 + j);
    float4 ho;
    float ht;
    ht = tanhf(px01.x + q01.x + b0.x + b1.x); ho.x = z01.x * hv.x + (1.0f - z01.x) * ht;
    ht = tanhf(px01.y + q01.y + b0.y + b1.y); ho.y = z01.y * hv.y + (1.0f - z01.y) * ht;
    ht = tanhf(px23.x + q23.x + b0.z + b1.z); ho.z = z23.x * hv.z + (1.0f - z23.x) * ht;
    ht = tanhf(px23.y + q23.y + b0.w + b1.w); ho.w = z23.y * hv.w + (1.0f - z23.y) * ht;
    ((float4*)out)[(size_t)m * 32 + j] = ho;
    if (hnext) {
        __half2 x0 = __floats2half2_rn(ho.x, ho.y), x1 = __floats2half2_rn(ho.z, ho.w);
        uint2 px; px.x = *(uint32_t*)&x0; px.y = *(uint32_t*)&x1;
        ((uint2*)g_xhh)[(size_t)m * 64 + j] = px;                 // x-half
        float4 hn = __ldg((const float4*)hnext + (size_t)m * 32 + j);
        __half2 n0 = __floats2half2_rn(hn.x, hn.y), n1 = __floats2half2_rn(hn.z, hn.w);
        uint2 pn; pn.x = *(uint32_t*)&n0; pn.y = *(uint32_t*)&n1;
        ((uint2*)g_xhh)[(size_t)m * 64 + 32 + j] = pn;            // h-half
    }
}

// ---------------- host ----------------
extern "C" void kernel_launch(void* const* d_in, const int* in_sizes, int n_in,
                              void* d_out, int out_size) {
    const float* x   = (const float*)d_in[0];
    const int*   ei  = (const int*)d_in[1];
    const float* ew  = (const float*)d_in[2];
    const float* h   = (const float*)d_in[3];
    const float* Wxz = (const float*)d_in[4];  const float* bxz = (const float*)d_in[5];
    const float* Whz = (const float*)d_in[6];  const float* bhz = (const float*)d_in[7];
    const float* Wxr = (const float*)d_in[8];  const float* bxr = (const float*)d_in[9];
    const float* Whr = (const float*)d_in[10]; const float* bhr = (const float*)d_in[11];
    const float* Wxh = (const float*)d_in[12]; const float* bxh = (const float*)d_in[13];
    const float* Whh = (const float*)d_in[14]; const float* bhh = (const float*)d_in[15];
    float* out = (float*)d_out;

    int N = in_sizes[0] / D;
    int E = in_sizes[2];
    int L = in_sizes[5] / D;

    const int* rowi = ei;
    const int* coli = ei + E;

    __half *p_axh, *p_aSr, *p_P, *p_Q, *p_w1h, *p_w1l, *p_w2h, *p_w2l;
    cudaGetSymbolAddress((void**)&p_axh, g_axh);
    cudaGetSymbolAddress((void**)&p_aSr, g_aSr);
    cudaGetSymbolAddress((void**)&p_P,   g_P);
    cudaGetSymbolAddress((void**)&p_Q,   g_Q);
    cudaGetSymbolAddress((void**)&p_w1h, g_W1h);
    cudaGetSymbolAddress((void**)&p_w1l, g_W1l);
    cudaGetSymbolAddress((void**)&p_w2h, g_W2h);
    cudaGetSymbolAddress((void**)&p_w2l, g_W2l);

    // A[128][K+16] + 2 x (Bh+Bl)[64][K+16] halves
    int smem1 = (128 * (256 + 16) + 2 * 2 * 64 * (256 + 16)) * 2;  // 208,896 B
    int smem2 = (128 * (128 + 16) + 2 * 2 * 64 * (128 + 16)) * 2;  // 110,592 B
    cudaFuncSetAttribute(k_wgemm, cudaFuncAttributeMaxDynamicSharedMemorySize, smem1);

    // ---- one-time: weight split (all layers), degrees, CSR build ----
    k_build_wt1<<<(L * 384 * 256 + 255) / 256, 256>>>(Wxz, Whz, Wxr, Whr, Wxh, L);
    k_build_wt2<<<(L * 128 * 128 + 255) / 256, 256>>>(Whh, L);
    k_deg_init<<<(N + 255) / 256, 256>>>(N);
    k_deg_edges<<<(E + 255) / 256, 256>>>(coli, ew, E);
    int nscan = (N + 1023) / 1024;
    k_scan1<<<nscan, 1024>>>(N);
    k_scan2<<<1, 64>>>(nscan);
    k_scan3<<<(N + 255) / 256, 256>>>(N);
    k_place<<<(E + 255) / 256, 256>>>(rowi, coli, ew, E);

    int nwblocks = (N * 32 + 255) / 256;  // warp per node
    int mtiles = (N + 127) / 128;

    k_prep<<<(N * 32 + 255) / 256, 256>>>(x, h, N);  // layer 0 pack only

    for (int i = 0; i < L; i++) {
        const float* hi = h + (size_t)i * N * D;
        const float* hnext = (i + 1 < L) ? h + (size_t)(i + 1) * N * D : nullptr;

        k_csr256<<<nwblocks, 256>>>(N);
        k_wgemm<<<mtiles, 256, smem1>>>(p_axh, p_w1h + (size_t)i * 384 * 256,
                                        p_w1l + (size_t)i * 384 * 256, p_P, N, 256, 384, 6, 4);
        k_gate<<<(N * 32 + 255) / 256, 256>>>(hi, bxz + i * D, bhz + i * D, bxr + i * D, bhr + i * D, N);
        k_csr128<<<nwblocks, 256>>>(N);
        k_wgemm<<<mtiles, 256, smem2>>>(p_aSr, p_w2h + (size_t)i * 128 * 128,
                                        p_w2l + (size_t)i * 128 * 128, p_Q, N, 128, 128, 2, 99);
        k_final<<<(N * 32 + 255) / 256, 256>>>(hi, bxh + i * D, bhh + i * D, hnext,
                                               out + (size_t)i * N * D, N);
    }
}

// round 13
// speedup vs baseline: 1.2031x; 1.0296x over previous
#include <cuda_runtime.h>
#include <cuda_fp16.h>
#include <mma.h>
#include <math.h>
#include <stdint.h>

using namespace nvcuda;

#define D 128
#define MAXN 50432
#define MAXE 1700000
#define LO_SCALE 1024.0f
#define INV_LO (1.0f / 1024.0f)
#define WFIX 1048576.0f
#define INV_WFIX (1.0f / 1048576.0f)

// ---------------- scratch (device globals: allocation-free) ----------------
__device__ float g_dinv[MAXN];
__device__ unsigned long long g_degpack[MAXN];
__device__ int   g_cnt[MAXN];
__device__ int   g_off[MAXN + 1];
__device__ int   g_cur[MAXN];
__device__ int   g_tmp[MAXN];
__device__ int   g_part[64];
__device__ int2  g_srt[MAXE];
__device__ __half g_xhh[(size_t)MAXN * 256];
__device__ __half g_rhh[(size_t)MAXN * D];
__device__ __half g_axh[(size_t)MAXN * 256];
__device__ __half g_aSr[(size_t)MAXN * D];
__device__ __half g_P[(size_t)MAXN * 384];
__device__ __half g_Q[(size_t)MAXN * D];
__device__ __half g_z[(size_t)MAXN * D];
__device__ __half g_W1h[2 * 384 * 256];
__device__ __half g_W1l[2 * 384 * 256];
__device__ __half g_W2h[2 * 128 * 128];
__device__ __half g_W2l[2 * 128 * 128];

__device__ __forceinline__ float sigmoidf(float x) { return 1.0f / (1.0f + __expf(-x)); }

__device__ __forceinline__ uint32_t smem_u32(const void* p) {
    uint32_t a;
    asm("{ .reg .u64 t; cvta.to.shared.u64 t, %1; cvt.u32.u64 %0, t; }" : "=r"(a) : "l"(p));
    return a;
}
#define CP_ASYNC16(dst, src) \
    asm volatile("cp.async.ca.shared.global [%0], [%1], 16;" :: "r"(dst), "l"(src) : "memory")
#define CP_COMMIT() asm volatile("cp.async.commit_group;" ::: "memory")
#define CP_WAIT0()  asm volatile("cp.async.wait_group 0;" ::: "memory")
#define CP_WAIT1()  asm volatile("cp.async.wait_group 1;" ::: "memory")

// ---------------- degree / histogram ----------------
__global__ void k_deg_init(int n) {
    int i = blockIdx.x * blockDim.x + threadIdx.x;
    if (i < n) g_degpack[i] = 0ULL;
}
__global__ void k_deg_edges(const int* __restrict__ coli, const float* __restrict__ w, int E) {
    int e = blockIdx.x * blockDim.x + threadIdx.x;
    if (e < E) {
        unsigned long long pk = (1ULL << 32) |
            (unsigned long long)(unsigned)__float2uint_rn(w[e] * WFIX);
        atomicAdd(&g_degpack[coli[e]], pk);
    }
}

// ---------------- multi-block scan (phase 1 unpacks degpack, finalizes dinv) ----------
__global__ void __launch_bounds__(1024)
k_scan1(int n) {
    __shared__ int warpsum[32];
    int i = blockIdx.x * 1024 + threadIdx.x;
    int lane = threadIdx.x & 31, wid = threadIdx.x >> 5;
    int v = 0;
    if (i < n) {
        unsigned long long pk = g_degpack[i];
        v = (int)(pk >> 32);
        float deg = (float)(unsigned)(pk & 0xffffffffULL) * INV_WFIX + 1.0f;
        g_dinv[i] = rsqrtf(deg);
        g_cnt[i] = v;
    }
    int x = v;
#pragma unroll
    for (int o = 1; o < 32; o <<= 1) {
        int t = __shfl_up_sync(~0u, x, o);
        if (lane >= o) x += t;
    }
    if (lane == 31) warpsum[wid] = x;
    __syncthreads();
    if (wid == 0) {
        int s = warpsum[lane];
#pragma unroll
        for (int o = 1; o < 32; o <<= 1) {
            int t = __shfl_up_sync(~0u, s, o);
            if (lane >= o) s += t;
        }
        warpsum[lane] = s;
    }
    __syncthreads();
    int incl = x + ((wid > 0) ? warpsum[wid - 1] : 0);
    if (i < n) g_tmp[i] = incl;
    if (threadIdx.x == 1023) g_part[blockIdx.x] = incl;
}
__global__ void k_scan2(int nb) {
    __shared__ int sm[64];
    int t = threadIdx.x;
    sm[t] = (t < nb) ? g_part[t] : 0;
    __syncthreads();
    for (int o = 1; o < 64; o <<= 1) {
        int v = (t >= o) ? sm[t - o] : 0;
        __syncthreads();
        sm[t] += v;
        __syncthreads();
    }
    g_part[t] = (t > 0) ? sm[t - 1] : 0;
}
__global__ void k_scan3(int n) {
    int i = blockIdx.x * blockDim.x + threadIdx.x;
    if (i >= n) return;
    int off = g_tmp[i] + g_part[i >> 10];
    g_off[i + 1] = off;
    g_cur[i] = off - g_cnt[i];
    if (i == 0) g_off[0] = 0;
}

// ---------------- placement scatter ----------------
__global__ void k_place(const int* __restrict__ rowi, const int* __restrict__ coli,
                        const float* __restrict__ w, int E) {
    int e = blockIdx.x * blockDim.x + threadIdx.x;
    if (e >= E) return;
    int r = rowi[e], c = coli[e];
    float nrm = w[e] * __ldg(g_dinv + r) * __ldg(g_dinv + c);
    int pos = atomicAdd(&g_cur[c], 1);
    g_srt[pos] = make_int2(r, __float_as_int(nrm));
}

// ---------------- weight build ----------------
__global__ void k_build_wt1(const float* __restrict__ Wxz, const float* __restrict__ Whz,
                            const float* __restrict__ Wxr, const float* __restrict__ Whr,
                            const float* __restrict__ Wxh, int L) {
    int idx = blockIdx.x * blockDim.x + threadIdx.x;
    if (idx >= L * 384 * 256) return;
    int layer = idx / (384 * 256);
    int rem = idx % (384 * 256);
    int n = rem / 256, k = rem % 256;
    int blk = n >> 7, nn = n & 127;
    size_t wo = (size_t)layer * D * D;
    float v;
    if (blk == 0)      v = (k < 128) ? Wxz[wo + k * 128 + nn] : Whz[wo + (k - 128) * 128 + nn];
    else if (blk == 1) v = (k < 128) ? Wxr[wo + k * 128 + nn] : Whr[wo + (k - 128) * 128 + nn];
    else               v = (k < 128) ? Wxh[wo + k * 128 + nn] : 0.0f;
    __half hi = __float2half_rn(v);
    g_W1h[idx] = hi;
    g_W1l[idx] = __float2half_rn((v - __half2float(hi)) * LO_SCALE);
}
__global__ void k_build_wt2(const float* __restrict__ Whh, int L) {
    int idx = blockIdx.x * blockDim.x + threadIdx.x;
    if (idx >= L * 128 * 128) return;
    int layer = idx / (128 * 128);
    int rem = idx % (128 * 128);
    int n = rem / 128, k = rem % 128;
    float v = Whh[(size_t)layer * D * D + k * 128 + n];
    __half hi = __float2half_rn(v);
    g_W2h[idx] = hi;
    g_W2l[idx] = __float2half_rn((v - __half2float(hi)) * LO_SCALE);
}

// ---------------- prep ----------------
__global__ void k_prep(const float* __restrict__ x, const float* __restrict__ h, int n) {
    int idx = blockIdx.x * blockDim.x + threadIdx.x;
    if (idx >= n * 32) return;
    int m = idx >> 5, j = idx & 31;
    const float4* src = (j < 16) ? (const float4*)x + (size_t)m * 32 + 2 * j
                                 : (const float4*)h + (size_t)m * 32 + 2 * (j - 16);
    float4 a = __ldg(src), b = __ldg(src + 1);
    __half2 h0 = __floats2half2_rn(a.x, a.y), h1 = __floats2half2_rn(a.z, a.w);
    __half2 h2 = __floats2half2_rn(b.x, b.y), h3 = __floats2half2_rn(b.z, b.w);
    uint4 o;
    o.x = *(uint32_t*)&h0; o.y = *(uint32_t*)&h1; o.z = *(uint32_t*)&h2; o.w = *(uint32_t*)&h3;
    ((uint4*)g_xhh)[(size_t)m * 32 + j] = o;
}

// ---------------- CSR gather 256 ----------------
__global__ void __launch_bounds__(256)
k_csr256(int n) {
    int node = (blockIdx.x * blockDim.x + threadIdx.x) >> 5;
    if (node >= n) return;
    int lane = threadIdx.x & 31;
    const uint4* src = (const uint4*)g_xhh;
    float di = __ldg(g_dinv + node);
    float s = di * di;
    float acc[8];
    {
        uint4 v = __ldg(src + (size_t)node * 32 + lane);
        float2 f0 = __half22float2(*(__half2*)&v.x), f1 = __half22float2(*(__half2*)&v.y);
        float2 f2 = __half22float2(*(__half2*)&v.z), f3 = __half22float2(*(__half2*)&v.w);
        acc[0] = s * f0.x; acc[1] = s * f0.y; acc[2] = s * f1.x; acc[3] = s * f1.y;
        acc[4] = s * f2.x; acc[5] = s * f2.y; acc[6] = s * f3.x; acc[7] = s * f3.y;
    }
    int e0 = __ldg(g_off + node), e1 = __ldg(g_off + node + 1);
#pragma unroll 4
    for (int e = e0; e < e1; e++) {
        int2 p = __ldg(g_srt + e);
        float nrm = __int_as_float(p.y);
        uint4 v = __ldg(src + (size_t)p.x * 32 + lane);
        float2 f0 = __half22float2(*(__half2*)&v.x), f1 = __half22float2(*(__half2*)&v.y);
        float2 f2 = __half22float2(*(__half2*)&v.z), f3 = __half22float2(*(__half2*)&v.w);
        acc[0] += nrm * f0.x; acc[1] += nrm * f0.y; acc[2] += nrm * f1.x; acc[3] += nrm * f1.y;
        acc[4] += nrm * f2.x; acc[5] += nrm * f2.y; acc[6] += nrm * f3.x; acc[7] += nrm * f3.y;
    }
    __half2 o0 = __floats2half2_rn(acc[0], acc[1]), o1 = __floats2half2_rn(acc[2], acc[3]);
    __half2 o2 = __floats2half2_rn(acc[4], acc[5]), o3 = __floats2half2_rn(acc[6], acc[7]);
    uint4 o;
    o.x = *(uint32_t*)&o0; o.y = *(uint32_t*)&o1; o.z = *(uint32_t*)&o2; o.w = *(uint32_t*)&o3;
    ((uint4*)g_axh)[(size_t)node * 32 + lane] = o;
}

// ---------------- CSR gather 128 ----------------
__global__ void __launch_bounds__(256)
k_csr128(int n) {
    int node = (blockIdx.x * blockDim.x + threadIdx.x) >> 5;
    if (node >= n) return;
    int lane = threadIdx.x & 31;
    const uint2* src = (const uint2*)g_rhh;
    float di = __ldg(g_dinv + node);
    float s = di * di;
    float acc[4];
    {
        uint2 v = __ldg(src + (size_t)node * 32 + lane);
        float2 f0 = __half22float2(*(__half2*)&v.x), f1 = __half22float2(*(__half2*)&v.y);
        acc[0] = s * f0.x; acc[1] = s * f0.y; acc[2] = s * f1.x; acc[3] = s * f1.y;
    }
    int e0 = __ldg(g_off + node), e1 = __ldg(g_off + node + 1);
#pragma unroll 4
    for (int e = e0; e < e1; e++) {
        int2 p = __ldg(g_srt + e);
        float nrm = __int_as_float(p.y);
        uint2 v = __ldg(src + (size_t)p.x * 32 + lane);
        float2 f0 = __half22float2(*(__half2*)&v.x), f1 = __half22float2(*(__half2*)&v.y);
        acc[0] += nrm * f0.x; acc[1] += nrm * f0.y; acc[2] += nrm * f1.x; acc[3] += nrm * f1.y;
    }
    __half2 o0 = __floats2half2_rn(acc[0], acc[1]), o1 = __floats2half2_rn(acc[2], acc[3]);
    uint2 o;
    o.x = *(uint32_t*)&o0; o.y = *(uint32_t*)&o1;
    ((uint2*)g_aSr)[(size_t)node * 32 + lane] = o;
}

// ---------------- WMMA fp16 GEMM (cp.async double-buffered, fp16 C) ----------------
__global__ void __launch_bounds__(256, 1)
k_wgemm(const __half* __restrict__ A, const __half* __restrict__ Bhi,
        const __half* __restrict__ Blo, __half* __restrict__ C,
        int M, int K, int ldC, int ntiles, int kredFrom) {
    extern __shared__ char smem[];
    const int tid = threadIdx.x;
    const int blockRow = blockIdx.x * 128;
    const int ldS = K + 16;

    __half* As = (__half*)smem;
    __half* Bbuf = As + 128 * ldS;
    const size_t BSTRIDE = (size_t)2 * 64 * ldS;

    const int K8 = K >> 3;

    auto prefetchB = [&](int nt) {
        int b = nt & 1;
        __half* Bh = Bbuf + (size_t)b * BSTRIDE;
        __half* Bl = Bh + 64 * ldS;
        int ktile = (nt >= kredFrom) ? 128 : K;
        int kt8 = ktile >> 3;
        int n0 = nt * 64;
        for (int idx = tid; idx < 64 * kt8; idx += 256) {
            int n = idx / kt8, c = (idx % kt8) * 8;
            CP_ASYNC16(smem_u32(Bh + (size_t)n * ldS + c), Bhi + (size_t)(n0 + n) * K + c);
            CP_ASYNC16(smem_u32(Bl + (size_t)n * ldS + c), Blo + (size_t)(n0 + n) * K + c);
        }
        CP_COMMIT();
    };

    prefetchB(0);

    for (int idx = tid; idx < 128 * K8; idx += 256) {
        int r = idx / K8, c = (idx % K8) * 8;
        uint4 v = __ldg((const uint4*)(A + (size_t)(blockRow + r) * K + c));
        *(uint4*)(As + (size_t)r * ldS + c) = v;
    }

    const int warpId = tid >> 5;
    const int wm = warpId & 3;
    const int wn = warpId >> 2;
    const int row0 = wm * 32;
    const int col0 = wn * 32;

    for (int nt = 0; nt < ntiles; nt++) {
        __syncthreads();
        if (nt + 1 < ntiles) {
            prefetchB(nt + 1);
            CP_WAIT1();
        } else {
            CP_WAIT0();
        }
        __syncthreads();

        int b = nt & 1;
        const __half* Bh = Bbuf + (size_t)b * BSTRIDE;
        const __half* Bl = Bh + 64 * ldS;
        const int n0 = nt * 64;
        const int ktile = (nt >= kredFrom) ? 128 : K;

        wmma::fragment<wmma::accumulator, 16, 16, 16, float> acch[2][2], accl[2][2];
#pragma unroll
        for (int i = 0; i < 2; i++)
#pragma unroll
            for (int j = 0; j < 2; j++) {
                wmma::fill_fragment(acch[i][j], 0.0f);
                wmma::fill_fragment(accl[i][j], 0.0f);
            }

        for (int k0 = 0; k0 < ktile; k0 += 16) {
            wmma::fragment<wmma::matrix_a, 16, 16, 16, __half, wmma::row_major> a[2];
            wmma::fragment<wmma::matrix_b, 16, 16, 16, __half, wmma::col_major> bh[2], bl[2];
#pragma unroll
            for (int i = 0; i < 2; i++)
                wmma::load_matrix_sync(a[i], As + (size_t)(row0 + i * 16) * ldS + k0, ldS);
#pragma unroll
            for (int j = 0; j < 2; j++) {
                wmma::load_matrix_sync(bh[j], Bh + (size_t)(col0 + j * 16) * ldS + k0, ldS);
                wmma::load_matrix_sync(bl[j], Bl + (size_t)(col0 + j * 16) * ldS + k0, ldS);
            }
#pragma unroll
            for (int i = 0; i < 2; i++)
#pragma unroll
                for (int j = 0; j < 2; j++) {
                    wmma::mma_sync(acch[i][j], a[i], bh[j], acch[i][j]);
                    wmma::mma_sync(accl[i][j], a[i], bl[j], accl[i][j]);
                }
        }

        __syncthreads();
        float* stage = (float*)(Bbuf + (size_t)b * BSTRIDE);
        const int ldSt = 68;
#pragma unroll
        for (int i = 0; i < 2; i++)
#pragma unroll
            for (int j = 0; j < 2; j++) {
#pragma unroll
                for (int t = 0; t < acch[i][j].num_elements; t++)
                    acch[i][j].x[t] += accl[i][j].x[t] * INV_LO;
                wmma::store_matrix_sync(stage + (size_t)(row0 + i * 16) * ldSt + col0 + j * 16,
                                        acch[i][j], ldSt, wmma::mem_row_major);
            }
        __syncthreads();
        for (int g = tid; g < 128 * 32; g += 256) {
            int r = g >> 5, c2 = (g & 31) * 2;
            float2 v = *(float2*)(stage + (size_t)r * ldSt + c2);
            __half2 hv = __floats2half2_rn(v.x, v.y);
            *(uint32_t*)(C + (size_t)(blockRow + r) * ldC + n0 + c2) = *(uint32_t*)&hv;
        }
    }
}

// ---------------- gates ----------------
__global__ void k_gate(const float* __restrict__ hi,
                       const float* __restrict__ bxz, const float* __restrict__ bhz,
                       const float* __restrict__ bxr, const float* __restrict__ bhr, int n) {
    int idx = blockIdx.x * blockDim.x + threadIdx.x;
    if (idx >= n * 32) return;
    int m = idx >> 5, j = idx & 31;
    const uint2* P2 = (const uint2*)g_P;
    uint2 pzu = P2[(size_t)m * 96 + j];
    uint2 pru = P2[(size_t)m * 96 + 32 + j];
    float2 pz01 = __half22float2(*(__half2*)&pzu.x), pz23 = __half22float2(*(__half2*)&pzu.y);
    float2 pr01 = __half22float2(*(__half2*)&pru.x), pr23 = __half22float2(*(__half2*)&pru.y);
    float4 b0 = __ldg((const float4*)bxz + j);
    float4 b1 = __ldg((const float4*)bhz + j);
    float4 b2 = __ldg((const float4*)bxr + j);
    float4 b3 = __ldg((const float4*)bhr + j);
    float4 hv = __ldg((const float4*)hi + (size_t)m * 32 + j);

    float z0 = sigmoidf(pz01.x + b0.x + b1.x), z1 = sigmoidf(pz01.y + b0.y + b1.y);
    float z2 = sigmoidf(pz23.x + b0.z + b1.z), z3 = sigmoidf(pz23.y + b0.w + b1.w);
    float r0 = sigmoidf(pr01.x + b2.x + b3.x), r1 = sigmoidf(pr01.y + b2.y + b3.y);
    float r2 = sigmoidf(pr23.x + b2.z + b3.z), r3 = sigmoidf(pr23.y + b2.w + b3.w);

    __half2 zo0 = __floats2half2_rn(z0, z1), zo1 = __floats2half2_rn(z2, z3);
    uint2 zo; zo.x = *(uint32_t*)&zo0; zo.y = *(uint32_t*)&zo1;
    ((uint2*)g_z)[(size_t)m * 32 + j] = zo;

    __half2 p0 = __floats2half2_rn(r0 * hv.x, r1 * hv.y);
    __half2 p1 = __floats2half2_rn(r2 * hv.z, r3 * hv.w);
    uint2 packed; packed.x = *(uint32_t*)&p0; packed.y = *(uint32_t*)&p1;
    ((uint2*)g_rhh)[(size_t)m * 32 + j] = packed;
}

// ---------------- final ----------------
__global__ void k_final(const float* __restrict__ hi,
                        const float* __restrict__ bxh, const float* __restrict__ bhh,
                        const float* __restrict__ hnext,
                        float* __restrict__ out, int n) {
    int idx = blockIdx.x * blockDim.x + threadIdx.x;
    if (idx >= n * 32) return;
    int m = idx >> 5, j = idx & 31;
    uint2 pxu = ((const uint2*)g_P)[(size_t)m * 96 + 64 + j];
    uint2 qu  = ((const uint2*)g_Q)[(size_t)m * 32 + j];
    uint2 zu  = ((const uint2*)g_z)[(size_t)m * 32 + j];
    float2 px01 = __half22float2(*(__half2*)&pxu.x), px23 = __half22float2(*(__half2*)&pxu.y);
    float2 q01  = __half22float2(*(__half2*)&qu.x),  q23  = __half22float2(*(__half2*)&qu.y);
    float2 z01  = __half22float2(*(__half2*)&zu.x),  z23  = __half22float2(*(__half2*)&zu.y);
    float4 b0 = __ldg((const float4*)bxh + j);
    float4 b1 = __ldg((const float4*)bhh + j);
    float4 hv = __ldg((const float4*)hi + (size_t)m * 32 + j);
    float4 ho;
    float ht;
    ht = tanhf(px01.x + q01.x + b0.x + b1.x); ho.x = z01.x * hv.x + (1.0f - z01.x) * ht;
    ht = tanhf(px01.y + q01.y + b0.y + b1.y); ho.y = z01.y * hv.y + (1.0f - z01.y) * ht;
    ht = tanhf(px23.x + q23.x + b0.z + b1.z); ho.z = z23.x * hv.z + (1.0f - z23.x) * ht;
    ht = tanhf(px23.y + q23.y + b0.w + b1.w); ho.w = z23.y * hv.w + (1.0f - z23.y) * ht;
    ((float4*)out)[(size_t)m * 32 + j] = ho;
    if (hnext) {
        __half2 x0 = __floats2half2_rn(ho.x, ho.y), x1 = __floats2half2_rn(ho.z, ho.w);
        uint2 px; px.x = *(uint32_t*)&x0; px.y = *(uint32_t*)&x1;
        ((uint2*)g_xhh)[(size_t)m * 64 + j] = px;
        float4 hn = __ldg((const float4*)hnext + (size_t)m * 32 + j);
        __half2 n0 = __floats2half2_rn(hn.x, hn.y), n1 = __floats2half2_rn(hn.z, hn.w);
        uint2 pn; pn.x = *(uint32_t*)&n0; pn.y = *(uint32_t*)&n1;
        ((uint2*)g_xhh)[(size_t)m * 64 + 32 + j] = pn;
    }
}

// ---------------- host ----------------
extern "C" void kernel_launch(void* const* d_in, const int* in_sizes, int n_in,
                              void* d_out, int out_size) {
    const float* x   = (const float*)d_in[0];
    const int*   ei  = (const int*)d_in[1];
    const float* ew  = (const float*)d_in[2];
    const float* h   = (const float*)d_in[3];
    const float* Wxz = (const float*)d_in[4];  const float* bxz = (const float*)d_in[5];
    const float* Whz = (const float*)d_in[6];  const float* bhz = (const float*)d_in[7];
    const float* Wxr = (const float*)d_in[8];  const float* bxr = (const float*)d_in[9];
    const float* Whr = (const float*)d_in[10]; const float* bhr = (const float*)d_in[11];
    const float* Wxh = (const float*)d_in[12]; const float* bxh = (const float*)d_in[13];
    const float* Whh = (const float*)d_in[14]; const float* bhh = (const float*)d_in[15];
    float* out = (float*)d_out;

    int N = in_sizes[0] / D;
    int E = in_sizes[2];
    int L = in_sizes[5] / D;

    const int* rowi = ei;
    const int* coli = ei + E;

    __half *p_axh, *p_aSr, *p_P, *p_Q, *p_w1h, *p_w1l, *p_w2h, *p_w2l;
    cudaGetSymbolAddress((void**)&p_axh, g_axh);
    cudaGetSymbolAddress((void**)&p_aSr, g_aSr);
    cudaGetSymbolAddress((void**)&p_P,   g_P);
    cudaGetSymbolAddress((void**)&p_Q,   g_Q);
    cudaGetSymbolAddress((void**)&p_w1h, g_W1h);
    cudaGetSymbolAddress((void**)&p_w1l, g_W1l);
    cudaGetSymbolAddress((void**)&p_w2h, g_W2h);
    cudaGetSymbolAddress((void**)&p_w2l, g_W2l);

    int smem1 = (128 * (256 + 16) + 2 * 2 * 64 * (256 + 16)) * 2;  // 208,896 B
    int smem2 = (128 * (128 + 16) + 2 * 2 * 64 * (128 + 16)) * 2;  // 110,592 B

    // lazily-created side stream + events (host objects only; captured work identical per call)
    static cudaStream_t s1 = nullptr;
    static cudaEvent_t evStart = nullptr, evSetup = nullptr;
    static cudaEvent_t evFork[4] = {}, evJoin[4] = {};
    if (!s1) {
        cudaFuncSetAttribute(k_wgemm, cudaFuncAttributeMaxDynamicSharedMemorySize, smem1);
        cudaStreamCreateWithFlags(&s1, cudaStreamNonBlocking);
        cudaEventCreateWithFlags(&evStart, cudaEventDisableTiming);
        cudaEventCreateWithFlags(&evSetup, cudaEventDisableTiming);
        for (int i = 0; i < 4; i++) {
            cudaEventCreateWithFlags(&evFork[i], cudaEventDisableTiming);
            cudaEventCreateWithFlags(&evJoin[i], cudaEventDisableTiming);
        }
    }

    // ---- setup: fork weight-split + prep onto s1, degree/CSR chain on origin ----
    cudaEventRecord(evStart, 0);
    cudaStreamWaitEvent(s1, evStart, 0);
    k_build_wt1<<<(L * 384 * 256 + 255) / 256, 256, 0, s1>>>(Wxz, Whz, Wxr, Whr, Wxh, L);
    k_build_wt2<<<(L * 128 * 128 + 255) / 256, 256, 0, s1>>>(Whh, L);
    k_prep<<<(N * 32 + 255) / 256, 256, 0, s1>>>(x, h, N);
    cudaEventRecord(evSetup, s1);

    k_deg_init<<<(N + 255) / 256, 256>>>(N);
    k_deg_edges<<<(E + 255) / 256, 256>>>(coli, ew, E);
    int nscan = (N + 1023) / 1024;
    k_scan1<<<nscan, 1024>>>(N);
    k_scan2<<<1, 64>>>(nscan);
    k_scan3<<<(N + 255) / 256, 256>>>(N);
    k_place<<<(E + 255) / 256, 256>>>(rowi, coli, ew, E);
    cudaStreamWaitEvent(0, evSetup, 0);   // join: csr256 needs g_xhh (prep) + weights

    int nwblocks = (N * 32 + 255) / 256;
    int mtiles = (N + 127) / 128;

    for (int i = 0; i < L; i++) {
        const float* hi = h + (size_t)i * N * D;
        const float* hnext = (i + 1 < L) ? h + (size_t)(i + 1) * N * D : nullptr;
        const __half* w1h = p_w1h + (size_t)i * 384 * 256;
        const __half* w1l = p_w1l + (size_t)i * 384 * 256;

        k_csr256<<<nwblocks, 256>>>(N);
        cudaEventRecord(evFork[i], 0);

        // fork: xh-part of GEMM1 (B rows 256..383, zero-padded -> K=128) on s1
        cudaStreamWaitEvent(s1, evFork[i], 0);
        k_wgemm<<<mtiles, 256, smem1, s1>>>(p_axh, w1h + (size_t)256 * 256,
                                            w1l + (size_t)256 * 256, p_P + 256,
                                            N, 256, 384, 2, 0);
        cudaEventRecord(evJoin[i], s1);

        // origin: z/r part (tiles 0..3, full K) -> gate -> csr128 -> GEMM2
        k_wgemm<<<mtiles, 256, smem1>>>(p_axh, w1h, w1l, p_P, N, 256, 384, 4, 99);
        k_gate<<<(N * 32 + 255) / 256, 256>>>(hi, bxz + i * D, bhz + i * D,
                                              bxr + i * D, bhr + i * D, N);
        k_csr128<<<nwblocks, 256>>>(N);
        k_wgemm<<<mtiles, 256, smem2>>>(p_aSr, p_w2h + (size_t)i * 128 * 128,
                                        p_w2l + (size_t)i * 128 * 128, p_Q, N, 128, 128, 2, 99);
        cudaStreamWaitEvent(0, evJoin[i], 0);  // join: final reads P xh block
        k_final<<<(N * 32 + 255) / 256, 256>>>(hi, bxh + i * D, bhh + i * D, hnext,
                                               out + (size_t)i * N * D, N);
    }
}